// round 15
// baseline (speedup 1.0000x reference)
#include <cuda_runtime.h>
#include <cuda_bf16.h>
#include <stdint.h>
#include <math.h>

// Problem constants
#define T_TOK 4096
#define HIDN  2048
#define NH    8
#define NKV   4
#define HD    256
#define SWIN  1024

// GEMM tiling (2-stage, 2 CTAs/SM)
#define GBK 32
#define GSTRIDE 40
#define GSTG (128 * GSTRIDE)

// Attention smem layout (bf16 element offsets)
#define DS   264
#define PSTR 72
#define ATT_QH 0
#define ATT_QL (64 * DS)
#define ATT_KH (2 * 64 * DS)
#define ATT_KL (3 * 64 * DS)
#define ATT_VH (4 * 64 * DS)
#define ATT_VL (5 * 64 * DS)
#define ATT_PH (6 * 64 * DS)
#define ATT_PL (ATT_PH + 64 * PSTR)
#define ATT_F  (ATT_PL + 64 * PSTR)
#define ATT_SMEM_BYTES (ATT_F * 2 + 512 * 4)

// Scratch (static device globals — allocation-free)
__device__ float g_qkv[T_TOK * 4096];    // split-K partial 0
__device__ float g_qkv2[T_TOK * 4096];   // split-K partial 1

__device__ __nv_bfloat16 sb_hid_hi[T_TOK * HIDN], sb_hid_lo[T_TOK * HIDN];
__device__ __nv_bfloat16 sb_w_hi[4096 * HIDN],    sb_w_lo[4096 * HIDN];  // [q;k;v]
__device__ __nv_bfloat16 sb_ow_hi[HIDN * HIDN],   sb_ow_lo[HIDN * HIDN];
__device__ __nv_bfloat16 sb_at_hi[T_TOK * HIDN],  sb_at_lo[T_TOK * HIDN];

__device__ __nv_bfloat16 sbq_hi[T_TOK * HIDN],     sbq_lo[T_TOK * HIDN];
__device__ __nv_bfloat16 sbk_hi[T_TOK * NKV * HD], sbk_lo[T_TOK * NKV * HD];
__device__ __nv_bfloat16 sbv_hi[T_TOK * NKV * HD], sbv_lo[T_TOK * NKV * HD];

// ---------------------------------------------------------------------------
#define LDSM4(R, addr) \
    asm volatile("ldmatrix.sync.aligned.m8n8.x4.shared.b16 {%0,%1,%2,%3}, [%4];" \
                 : "=r"((R)[0]), "=r"((R)[1]), "=r"((R)[2]), "=r"((R)[3]) : "r"(addr))

#define LDSM4T(R, addr) \
    asm volatile("ldmatrix.sync.aligned.m8n8.x4.trans.shared.b16 {%0,%1,%2,%3}, [%4];" \
                 : "=r"((R)[0]), "=r"((R)[1]), "=r"((R)[2]), "=r"((R)[3]) : "r"(addr))

#define MMA16816(Cacc, A, b0, b1) \
    asm volatile("mma.sync.aligned.m16n8k16.row.col.f32.bf16.bf16.f32 " \
                 "{%0,%1,%2,%3}, {%4,%5,%6,%7}, {%8,%9}, {%0,%1,%2,%3};" \
                 : "+f"((Cacc)[0]), "+f"((Cacc)[1]), "+f"((Cacc)[2]), "+f"((Cacc)[3]) \
                 : "r"((A)[0]), "r"((A)[1]), "r"((A)[2]), "r"((A)[3]), "r"(b0), "r"(b1))

#define CPA16(dst, src) \
    asm volatile("cp.async.cg.shared.global [%0], [%1], 16;" :: "r"(dst), "l"(src))

__device__ __forceinline__ unsigned int smem_u32(const void* p) {
    return (unsigned int)__cvta_generic_to_shared(p);
}

// ---------------------------------------------------------------------------
// Fused split: all 5 tensors in one launch, 4 float4s per thread (MLP=4).
// ---------------------------------------------------------------------------
struct SplitSegs {
    const float4* src[5];
    __nv_bfloat162* hi[5];
    __nv_bfloat162* lo[5];
    long end[5];
};

__global__ __launch_bounds__(256) void split_all_kernel(SplitSegs segs)
{
    long base = ((long)blockIdx.x * blockDim.x + threadIdx.x) * 4;
    if (base >= segs.end[4]) return;
    int s = 0;
    while (base >= segs.end[s]) ++s;
    long start = (s == 0) ? 0 : segs.end[s - 1];
    long loc = base - start;
    const float4* src = segs.src[s] + loc;
    __nv_bfloat162* hi = segs.hi[s] + 2 * loc;
    __nv_bfloat162* lo = segs.lo[s] + 2 * loc;
#pragma unroll
    for (int j = 0; j < 4; ++j) {
        float4 v = src[j];
        __nv_bfloat16 h0 = __float2bfloat16_rn(v.x);
        __nv_bfloat16 h1 = __float2bfloat16_rn(v.y);
        __nv_bfloat16 h2 = __float2bfloat16_rn(v.z);
        __nv_bfloat16 h3 = __float2bfloat16_rn(v.w);
        hi[2 * j]     = __halves2bfloat162(h0, h1);
        hi[2 * j + 1] = __halves2bfloat162(h2, h3);
        lo[2 * j]     = __halves2bfloat162(
            __float2bfloat16_rn(v.x - __bfloat162float(h0)),
            __float2bfloat16_rn(v.y - __bfloat162float(h1)));
        lo[2 * j + 1] = __halves2bfloat162(
            __float2bfloat16_rn(v.z - __bfloat162float(h2)),
            __float2bfloat16_rn(v.w - __bfloat162float(h3)));
    }
}

// ---------------------------------------------------------------------------
// Split-bf16 tensor-core NT GEMM, 2-stage cp.async, 2 CTAs/SM.
// Split-K via blockIdx.z: z selects K-range [z*Kred, (z+1)*Kred) and output
// buffer (C0 for z=0, C1 for z=1). ld = row stride of A/B in elements.
// ---------------------------------------------------------------------------
__global__ __launch_bounds__(256, 2) void gemm_bf16split(
    const __nv_bfloat16* __restrict__ Ah, const __nv_bfloat16* __restrict__ Al,
    const __nv_bfloat16* __restrict__ Bh, const __nv_bfloat16* __restrict__ Bl,
    float* __restrict__ C0, float* __restrict__ C1,
    int M, int N, int Kred, int ld)
{
    extern __shared__ __nv_bfloat16 sm[];
    const int tid = threadIdx.x;
    const int bm = blockIdx.y * 128, bn = blockIdx.x * 128;
    const int koff = blockIdx.z * Kred;
    float* __restrict__ C = blockIdx.z ? C1 : C0;
    const int lane = tid & 31, wid = tid >> 5;
    const int wm = wid & 3, wn = wid >> 2;

#define GEMM_ISSUE(buf, k0)                                                          \
    {                                                                                \
        __nv_bfloat16* base = sm + (buf) * 4 * GSTG;                                 \
        _Pragma("unroll")                                                            \
        for (int half = 0; half < 2; ++half) {                                       \
            int c = tid + half * 256;                                                \
            int row = c >> 2, cc = c & 3;                                            \
            unsigned int sA = smem_u32(base + row * GSTRIDE + cc * 8);               \
            const __nv_bfloat16* gAh = Ah + (size_t)(bm + row) * ld + koff + (k0) + cc*8; \
            const __nv_bfloat16* gAl = Al + (size_t)(bm + row) * ld + koff + (k0) + cc*8; \
            const __nv_bfloat16* gBh = Bh + (size_t)(bn + row) * ld + koff + (k0) + cc*8; \
            const __nv_bfloat16* gBl = Bl + (size_t)(bn + row) * ld + koff + (k0) + cc*8; \
            CPA16(sA, gAh);                                                          \
            CPA16(sA + GSTG * 2, gAl);                                               \
            CPA16(sA + GSTG * 4, gBh);                                               \
            CPA16(sA + GSTG * 6, gBl);                                               \
        }                                                                            \
        asm volatile("cp.async.commit_group;");                                      \
    }

    float acc[16][4];
#pragma unroll
    for (int t = 0; t < 16; ++t)
#pragma unroll
        for (int j = 0; j < 4; ++j) acc[t][j] = 0.f;

    GEMM_ISSUE(0, 0);

    const int iters = Kred / GBK;
    for (int it = 0; it < iters; ++it) {
        asm volatile("cp.async.wait_group 0;");
        __syncthreads();
        if (it + 1 < iters)
            GEMM_ISSUE((it + 1) & 1, (it + 1) * GBK);

        const __nv_bfloat16* st = sm + (it & 1) * 4 * GSTG;
#pragma unroll
        for (int ks = 0; ks < 2; ++ks) {
            unsigned int ah[2][4], al[2][4];
#pragma unroll
            for (int mt = 0; mt < 2; ++mt) {
                int row = wm * 32 + mt * 16 + (lane & 15);
                int col = ks * 16 + (lane >> 4) * 8;
                unsigned int ad = smem_u32(st + row * GSTRIDE + col);
                LDSM4(ah[mt], ad);
                LDSM4(al[mt], ad + GSTG * 2);
            }
#pragma unroll
            for (int p = 0; p < 4; ++p) {
                int r = lane & 7, g = lane >> 3;
                int nrow = wn * 64 + p * 16 + ((g >> 1) & 1) * 8 + r;
                int col = ks * 16 + (g & 1) * 8;
                unsigned int bd = smem_u32(st + 2 * GSTG + nrow * GSTRIDE + col);
                unsigned int bh[4], bl[4];
                LDSM4(bh, bd);
                LDSM4(bl, bd + GSTG * 2);
#pragma unroll
                for (int mt = 0; mt < 2; ++mt)
#pragma unroll
                    for (int o = 0; o < 4; o += 2)
                        MMA16816(acc[mt * 8 + p * 2 + (o >> 1)],
                                 ah[mt], bh[o], bh[o + 1]);
#pragma unroll
                for (int mt = 0; mt < 2; ++mt)
#pragma unroll
                    for (int o = 0; o < 4; o += 2)
                        MMA16816(acc[mt * 8 + p * 2 + (o >> 1)],
                                 ah[mt], bl[o], bl[o + 1]);
#pragma unroll
                for (int mt = 0; mt < 2; ++mt)
#pragma unroll
                    for (int o = 0; o < 4; o += 2)
                        MMA16816(acc[mt * 8 + p * 2 + (o >> 1)],
                                 al[mt], bh[o], bh[o + 1]);
            }
        }
    }

#pragma unroll
    for (int mt = 0; mt < 2; ++mt)
#pragma unroll
        for (int nt = 0; nt < 8; ++nt) {
            float* cc = acc[mt * 8 + nt];
            int r = bm + wm * 32 + mt * 16 + (lane >> 2);
            int cl = bn + wn * 64 + nt * 8 + (lane & 3) * 2;
            *(float2*)&C[(size_t)r * N + cl]       = make_float2(cc[0], cc[1]);
            *(float2*)&C[(size_t)(r + 8) * N + cl] = make_float2(cc[2], cc[3]);
        }
#undef GEMM_ISSUE
}

// ---------------------------------------------------------------------------
// RMSNorm (+weight) + RoPE, warp-per-role.
// Reads g_qkv + g_qkv2 (split-K partial sums) and reduces on the fly.
// ---------------------------------------------------------------------------
__device__ __forceinline__ void store_hl4(__nv_bfloat16* dh, __nv_bfloat16* dl,
                                          size_t off, float4 v)
{
    __nv_bfloat16 h0 = __float2bfloat16_rn(v.x), h1 = __float2bfloat16_rn(v.y);
    __nv_bfloat16 h2 = __float2bfloat16_rn(v.z), h3 = __float2bfloat16_rn(v.w);
    union { __nv_bfloat162 b[2]; uint2 u; } ph, pl;
    ph.b[0] = __halves2bfloat162(h0, h1);
    ph.b[1] = __halves2bfloat162(h2, h3);
    pl.b[0] = __halves2bfloat162(__float2bfloat16_rn(v.x - __bfloat162float(h0)),
                                 __float2bfloat16_rn(v.y - __bfloat162float(h1)));
    pl.b[1] = __halves2bfloat162(__float2bfloat16_rn(v.z - __bfloat162float(h2)),
                                 __float2bfloat16_rn(v.w - __bfloat162float(h3)));
    *(uint2*)(dh + off) = ph.u;
    *(uint2*)(dl + off) = pl.u;
}

__global__ __launch_bounds__(256) void norm_rope_kernel(
    const float* __restrict__ cosv, const float* __restrict__ sinv,
    const float* __restrict__ q_nw, const float* __restrict__ k_nw)
{
    const int t = blockIdx.x;
    const int wid = threadIdx.x >> 5, lane = threadIdx.x & 31;
    const int cA = lane * 4, cB = 128 + lane * 4;

#pragma unroll
    for (int rr = 0; rr < 2; ++rr) {
        const int role = wid * 2 + rr;
        size_t soff;
        const float* w = nullptr;
        bool rope = true;
        __nv_bfloat16 *dh, *dl;
        size_t doff;
        if (role < 8) {
            soff = (size_t)t * 4096 + role * HD; w = q_nw;
            dh = sbq_hi; dl = sbq_lo; doff = (size_t)t * HIDN + role * HD;
        } else if (role < 12) {
            soff = (size_t)t * 4096 + 2048 + (role - 8) * HD; w = k_nw;
            dh = sbk_hi; dl = sbk_lo; doff = (size_t)t * 1024 + (role - 8) * HD;
        } else {
            soff = (size_t)t * 4096 + 3072 + (role - 12) * HD; rope = false;
            dh = sbv_hi; dl = sbv_lo; doff = (size_t)t * 1024 + (role - 12) * HD;
        }
        const float* s0 = g_qkv + soff;
        const float* s1 = g_qkv2 + soff;

        float4 a = *(const float4*)(s0 + cA);
        float4 b = *(const float4*)(s0 + cB);
        float4 a2 = *(const float4*)(s1 + cA);
        float4 b2 = *(const float4*)(s1 + cB);
        a.x += a2.x; a.y += a2.y; a.z += a2.z; a.w += a2.w;
        b.x += b2.x; b.y += b2.y; b.z += b2.z; b.w += b2.w;

        float ss = a.x*a.x + a.y*a.y + a.z*a.z + a.w*a.w
                 + b.x*b.x + b.y*b.y + b.z*b.z + b.w*b.w;
#pragma unroll
        for (int o = 16; o >= 1; o >>= 1) ss += __shfl_xor_sync(0xffffffffu, ss, o);
        float rn = rsqrtf(ss * (1.f / HD) + 1e-6f);

        float4 ya, yb;
        if (w) {
            float4 wa = *(const float4*)(w + cA);
            float4 wb = *(const float4*)(w + cB);
            ya = make_float4(a.x*rn*wa.x, a.y*rn*wa.y, a.z*rn*wa.z, a.w*rn*wa.w);
            yb = make_float4(b.x*rn*wb.x, b.y*rn*wb.y, b.z*rn*wb.z, b.w*rn*wb.w);
        } else {
            ya = make_float4(a.x*rn, a.y*rn, a.z*rn, a.w*rn);
            yb = make_float4(b.x*rn, b.y*rn, b.z*rn, b.w*rn);
        }

        float4 oa = ya, ob = yb;
        if (rope) {
            const float* cp = cosv + (size_t)t * HD;
            const float* sp = sinv + (size_t)t * HD;
            float4 ca = *(const float4*)(cp + cA), cb = *(const float4*)(cp + cB);
            float4 sa = *(const float4*)(sp + cA), sb = *(const float4*)(sp + cB);
            oa = make_float4(ya.x*ca.x - yb.x*sa.x, ya.y*ca.y - yb.y*sa.y,
                             ya.z*ca.z - yb.z*sa.z, ya.w*ca.w - yb.w*sa.w);
            ob = make_float4(yb.x*cb.x + ya.x*sb.x, yb.y*cb.y + ya.y*sb.y,
                             yb.z*cb.z + ya.z*sb.z, yb.w*cb.w + ya.w*sb.w);
        }
        store_hl4(dh, dl, doff + cA, oa);
        store_hl4(dh, dl, doff + cB, ob);
    }
}

// ---------------------------------------------------------------------------
// Sliding-window flash attention (best-measured R9/R11 variant, 256 threads).
// ---------------------------------------------------------------------------
__global__ __launch_bounds__(256) void attn_mma_kernel(
    const __nv_bfloat16* __restrict__ Qh, const __nv_bfloat16* __restrict__ Ql,
    const __nv_bfloat16* __restrict__ Kh, const __nv_bfloat16* __restrict__ Kl,
    const __nv_bfloat16* __restrict__ Vh, const __nv_bfloat16* __restrict__ Vl,
    __nv_bfloat16* __restrict__ Oh, __nv_bfloat16* __restrict__ Ol)
{
    extern __shared__ __nv_bfloat16 sm[];
    float* fb   = (float*)(sm + ATT_F);
    float* pmax = fb + 256;
    float* psum = fb + 384;

    const int qb = blockIdx.x, h = blockIdx.y;
    const int q0 = qb * 64;
    const int kvh = h >> 1;
    const int tid = threadIdx.x;
    const int lane = tid & 31, wid = tid >> 5;
    const int wm = wid & 3, wn = wid >> 2;
    const int wm2 = wid & 1, wn2 = wid >> 1;

    if (tid < 64) { fb[tid] = -1e30f; fb[128 + tid] = 0.f; }

#define ISSUE_K(k0)                                                            \
    {                                                                          \
        for (int i = tid; i < 2048; i += 256) {                                \
            int r = i >> 5, c = (i & 31) * 8;                                  \
            size_t g = (size_t)((k0) + r) * (NKV * HD) + kvh * HD + c;         \
            CPA16(smem_u32(sm + ATT_KH + r * DS + c), Kh + g);                 \
            CPA16(smem_u32(sm + ATT_KL + r * DS + c), Kl + g);                 \
        }                                                                      \
        asm volatile("cp.async.commit_group;");                                \
    }
#define ISSUE_V(k0)                                                            \
    {                                                                          \
        for (int i = tid; i < 2048; i += 256) {                                \
            int r = i >> 5, c = (i & 31) * 8;                                  \
            size_t g = (size_t)((k0) + r) * (NKV * HD) + kvh * HD + c;         \
            CPA16(smem_u32(sm + ATT_VH + r * DS + c), Vh + g);                 \
            CPA16(smem_u32(sm + ATT_VL + r * DS + c), Vl + g);                 \
        }                                                                      \
        asm volatile("cp.async.commit_group;");                                \
    }

    for (int i = tid; i < 2048; i += 256) {
        int r = i >> 5, c = (i & 31) * 8;
        size_t g = (size_t)(q0 + r) * HIDN + h * HD + c;
        CPA16(smem_u32(sm + ATT_QH + r * DS + c), Qh + g);
        CPA16(smem_u32(sm + ATT_QL + r * DS + c), Ql + g);
    }
    asm volatile("cp.async.commit_group;");

    float o_acc[2][8][4];
#pragma unroll
    for (int mt = 0; mt < 2; ++mt)
#pragma unroll
        for (int nt = 0; nt < 8; ++nt)
#pragma unroll
            for (int e = 0; e < 4; ++e) o_acc[mt][nt][e] = 0.f;

    int jmin = q0 - (SWIN - 1); if (jmin < 0) jmin = 0;
    const int t0 = jmin >> 6;
    const int t1 = (q0 + 63) >> 6;
    const int ntiles = t1 - t0 + 1;

    ISSUE_K(t0 * 64);
    ISSUE_V(t0 * 64);
    asm volatile("cp.async.wait_group 1;");
    __syncthreads();

    for (int kt = t0; kt <= t1; ++kt) {
        const int k0 = kt * 64;
        const int pp = (kt - t0) & 1;
        float* m_old = fb + pp * 64;
        float* m_newp = fb + (pp ^ 1) * 64;
        float* l_old = fb + 128 + pp * 64;
        float* l_newp = fb + 128 + (pp ^ 1) * 64;

        // ---- Phase 1: S = Q K^T ----
        float sacc[4][4];
#pragma unroll
        for (int nt = 0; nt < 4; ++nt)
#pragma unroll
            for (int e = 0; e < 4; ++e) sacc[nt][e] = 0.f;

#pragma unroll 4
        for (int ks = 0; ks < 16; ++ks) {
            unsigned int ah[4], al[4];
            {
                int row = wm * 16 + (lane & 15);
                int col = ks * 16 + (lane >> 4) * 8;
                LDSM4(ah, smem_u32(sm + ATT_QH + row * DS + col));
                LDSM4(al, smem_u32(sm + ATT_QL + row * DS + col));
            }
            unsigned int bh[2][4], bl[2][4];
#pragma unroll
            for (int p = 0; p < 2; ++p) {
                int nrow = wn * 32 + p * 16 + ((lane >> 4) << 3) + (lane & 7);
                int col = ks * 16 + ((lane >> 3) & 1) * 8;
                LDSM4(bh[p], smem_u32(sm + ATT_KH + nrow * DS + col));
                LDSM4(bl[p], smem_u32(sm + ATT_KL + nrow * DS + col));
            }
#pragma unroll
            for (int p = 0; p < 2; ++p)
#pragma unroll
                for (int o = 0; o < 4; o += 2)
                    MMA16816(sacc[p * 2 + (o >> 1)], ah, bh[p][o], bh[p][o + 1]);
#pragma unroll
            for (int p = 0; p < 2; ++p)
#pragma unroll
                for (int o = 0; o < 4; o += 2)
                    MMA16816(sacc[p * 2 + (o >> 1)], ah, bl[p][o], bl[p][o + 1]);
#pragma unroll
            for (int p = 0; p < 2; ++p)
#pragma unroll
                for (int o = 0; o < 4; o += 2)
                    MMA16816(sacc[p * 2 + (o >> 1)], al, bh[p][o], bh[p][o + 1]);
        }

        // Mask
        const int r_lo = q0 + wm * 16 + (lane >> 2);
        const int r_hi = r_lo + 8;
#pragma unroll
        for (int nt = 0; nt < 4; ++nt) {
#pragma unroll
            for (int e = 0; e < 2; ++e) {
                int j = k0 + wn * 32 + nt * 8 + (lane & 3) * 2 + e;
                if (!(j <= r_lo && r_lo - j < SWIN)) sacc[nt][e] = -1e30f;
                if (!(j <= r_hi && r_hi - j < SWIN)) sacc[nt][e + 2] = -1e30f;
            }
        }

        float mx0 = -1e30f, mx1 = -1e30f;
#pragma unroll
        for (int nt = 0; nt < 4; ++nt) {
            mx0 = fmaxf(mx0, fmaxf(sacc[nt][0], sacc[nt][1]));
            mx1 = fmaxf(mx1, fmaxf(sacc[nt][2], sacc[nt][3]));
        }
        mx0 = fmaxf(mx0, __shfl_xor_sync(0xffffffffu, mx0, 1));
        mx0 = fmaxf(mx0, __shfl_xor_sync(0xffffffffu, mx0, 2));
        mx1 = fmaxf(mx1, __shfl_xor_sync(0xffffffffu, mx1, 1));
        mx1 = fmaxf(mx1, __shfl_xor_sync(0xffffffffu, mx1, 2));
        if ((lane & 3) == 0) {
            pmax[wn * 64 + wm * 16 + (lane >> 2)]     = mx0;
            pmax[wn * 64 + wm * 16 + 8 + (lane >> 2)] = mx1;
        }
        __syncthreads();

        if (kt < t1) ISSUE_K(k0 + 64);

        float mo_t = 0.f, mn_t = 0.f;
        if (tid < 64) {
            mo_t = m_old[tid];
            mn_t = fmaxf(mo_t, fmaxf(pmax[tid], pmax[64 + tid]));
            m_newp[tid] = mn_t;
        }
        {
            const int pr0 = wm * 16 + (lane >> 2);
            const int pr1 = pr0 + 8;
            float m0v = fmaxf(m_old[pr0], fmaxf(pmax[pr0], pmax[64 + pr0]));
            float m1v = fmaxf(m_old[pr1], fmaxf(pmax[pr1], pmax[64 + pr1]));
            float s0 = 0.f, s1 = 0.f;
#pragma unroll
            for (int nt = 0; nt < 4; ++nt) {
                float p00 = (sacc[nt][0] > -1e29f) ? __expf(sacc[nt][0] - m0v) : 0.f;
                float p01 = (sacc[nt][1] > -1e29f) ? __expf(sacc[nt][1] - m0v) : 0.f;
                float p10 = (sacc[nt][2] > -1e29f) ? __expf(sacc[nt][2] - m1v) : 0.f;
                float p11 = (sacc[nt][3] > -1e29f) ? __expf(sacc[nt][3] - m1v) : 0.f;
                s0 += p00 + p01; s1 += p10 + p11;
                int colb = wn * 32 + nt * 8 + (lane & 3) * 2;
                __nv_bfloat16 h00 = __float2bfloat16_rn(p00);
                __nv_bfloat16 h01 = __float2bfloat16_rn(p01);
                __nv_bfloat16 h10 = __float2bfloat16_rn(p10);
                __nv_bfloat16 h11 = __float2bfloat16_rn(p11);
                *(__nv_bfloat162*)(sm + ATT_PH + pr0 * PSTR + colb) =
                    __halves2bfloat162(h00, h01);
                *(__nv_bfloat162*)(sm + ATT_PH + pr1 * PSTR + colb) =
                    __halves2bfloat162(h10, h11);
                *(__nv_bfloat162*)(sm + ATT_PL + pr0 * PSTR + colb) =
                    __halves2bfloat162(
                        __float2bfloat16_rn(p00 - __bfloat162float(h00)),
                        __float2bfloat16_rn(p01 - __bfloat162float(h01)));
                *(__nv_bfloat162*)(sm + ATT_PL + pr1 * PSTR + colb) =
                    __halves2bfloat162(
                        __float2bfloat16_rn(p10 - __bfloat162float(h10)),
                        __float2bfloat16_rn(p11 - __bfloat162float(h11)));
            }
            s0 += __shfl_xor_sync(0xffffffffu, s0, 1);
            s0 += __shfl_xor_sync(0xffffffffu, s0, 2);
            s1 += __shfl_xor_sync(0xffffffffu, s1, 1);
            s1 += __shfl_xor_sync(0xffffffffu, s1, 2);
            if ((lane & 3) == 0) {
                psum[wn * 64 + wm * 16 + (lane >> 2)]     = s0;
                psum[wn * 64 + wm * 16 + 8 + (lane >> 2)] = s1;
            }
        }

        // Rescale O while V(t) finishes loading
#pragma unroll
        for (int mt = 0; mt < 2; ++mt) {
            int r0 = wm2 * 32 + mt * 16 + (lane >> 2);
            int r1 = r0 + 8;
            float a0 = m_old[r0];
            float sL = __expf(a0 - fmaxf(a0, fmaxf(pmax[r0], pmax[64 + r0])));
            float a1 = m_old[r1];
            float sH = __expf(a1 - fmaxf(a1, fmaxf(pmax[r1], pmax[64 + r1])));
#pragma unroll
            for (int nt = 0; nt < 8; ++nt) {
                o_acc[mt][nt][0] *= sL; o_acc[mt][nt][1] *= sL;
                o_acc[mt][nt][2] *= sH; o_acc[mt][nt][3] *= sH;
            }
        }

        if (kt < t1) { asm volatile("cp.async.wait_group 1;"); }
        else         { asm volatile("cp.async.wait_group 0;"); }
        __syncthreads();

        if (tid < 64)
            l_newp[tid] = l_old[tid] * __expf(mo_t - mn_t)
                          + psum[tid] + psum[64 + tid];

        // ---- Phase 2: O += P V ----
#pragma unroll
        for (int ks2 = 0; ks2 < 4; ++ks2) {
            unsigned int aph[2][4], apl[2][4];
#pragma unroll
            for (int mt = 0; mt < 2; ++mt) {
                int row = wm2 * 32 + mt * 16 + (lane & 15);
                int col = ks2 * 16 + (lane >> 4) * 8;
                LDSM4(aph[mt], smem_u32(sm + ATT_PH + row * PSTR + col));
                LDSM4(apl[mt], smem_u32(sm + ATT_PL + row * PSTR + col));
            }
#pragma unroll
            for (int ng = 0; ng < 4; ++ng) {
                int vr = ks2 * 16 + ((lane >> 3) & 1) * 8 + (lane & 7);
                int vc = wn2 * 64 + ng * 16 + (lane >> 4) * 8;
                unsigned int bvh[4], bvl[4];
                LDSM4T(bvh, smem_u32(sm + ATT_VH + vr * DS + vc));
                LDSM4T(bvl, smem_u32(sm + ATT_VL + vr * DS + vc));
#pragma unroll
                for (int mt = 0; mt < 2; ++mt)
#pragma unroll
                    for (int o = 0; o < 4; o += 2)
                        MMA16816(o_acc[mt][ng * 2 + (o >> 1)],
                                 aph[mt], bvh[o], bvh[o + 1]);
#pragma unroll
                for (int mt = 0; mt < 2; ++mt)
#pragma unroll
                    for (int o = 0; o < 4; o += 2)
                        MMA16816(o_acc[mt][ng * 2 + (o >> 1)],
                                 aph[mt], bvl[o], bvl[o + 1]);
#pragma unroll
                for (int mt = 0; mt < 2; ++mt)
#pragma unroll
                    for (int o = 0; o < 4; o += 2)
                        MMA16816(o_acc[mt][ng * 2 + (o >> 1)],
                                 apl[mt], bvh[o], bvh[o + 1]);
            }
        }
        __syncthreads();

        if (kt < t1) {
            ISSUE_V(k0 + 64);
            asm volatile("cp.async.wait_group 1;");
            __syncthreads();
        }
    }

    // Epilogue
    float* l_fin = fb + 128 + (ntiles & 1) * 64;
#pragma unroll
    for (int mt = 0; mt < 2; ++mt) {
        int rL = wm2 * 32 + mt * 16 + (lane >> 2);
        int rH = rL + 8;
        float invL = 1.f / l_fin[rL];
        float invH = 1.f / l_fin[rH];
#pragma unroll
        for (int nt = 0; nt < 8; ++nt) {
            int col = wn2 * 64 + nt * 8 + (lane & 3) * 2;
            size_t gL = (size_t)(q0 + rL) * HIDN + h * HD + col;
            size_t gH = (size_t)(q0 + rH) * HIDN + h * HD + col;
            float v0 = o_acc[mt][nt][0] * invL, v1 = o_acc[mt][nt][1] * invL;
            float v2 = o_acc[mt][nt][2] * invH, v3 = o_acc[mt][nt][3] * invH;
            __nv_bfloat16 h0 = __float2bfloat16_rn(v0), h1 = __float2bfloat16_rn(v1);
            __nv_bfloat16 h2 = __float2bfloat16_rn(v2), h3 = __float2bfloat16_rn(v3);
            *(__nv_bfloat162*)(Oh + gL) = __halves2bfloat162(h0, h1);
            *(__nv_bfloat162*)(Oh + gH) = __halves2bfloat162(h2, h3);
            *(__nv_bfloat162*)(Ol + gL) = __halves2bfloat162(
                __float2bfloat16_rn(v0 - __bfloat162float(h0)),
                __float2bfloat16_rn(v1 - __bfloat162float(h1)));
            *(__nv_bfloat162*)(Ol + gH) = __halves2bfloat162(
                __float2bfloat16_rn(v2 - __bfloat162float(h2)),
                __float2bfloat16_rn(v3 - __bfloat162float(h3)));
        }
    }
#undef ISSUE_K
#undef ISSUE_V
}

// ---------------------------------------------------------------------------
extern "C" void kernel_launch(void* const* d_in, const int* in_sizes, int n_in,
                              void* d_out, int out_size)
{
    const float* hidden = (const float*)d_in[0];
    const float* cosv   = (const float*)d_in[1];
    const float* sinv   = (const float*)d_in[2];
    const float* q_w    = (const float*)d_in[3];
    const float* k_w    = (const float*)d_in[4];
    const float* v_w    = (const float*)d_in[5];
    const float* o_w    = (const float*)d_in[6];
    const float* q_nw   = (const float*)d_in[7];
    const float* k_nw   = (const float*)d_in[8];

    float *qkvp, *qkv2p;
    cudaGetSymbolAddress((void**)&qkvp, g_qkv);
    cudaGetSymbolAddress((void**)&qkv2p, g_qkv2);

    __nv_bfloat16 *hid_h, *hid_l, *w_h, *w_l, *ow_h, *ow_l, *at_h, *at_l,
                  *q_h, *q_l, *k_h, *k_l, *v_h, *v_l;
    cudaGetSymbolAddress((void**)&hid_h, sb_hid_hi);
    cudaGetSymbolAddress((void**)&hid_l, sb_hid_lo);
    cudaGetSymbolAddress((void**)&w_h, sb_w_hi);
    cudaGetSymbolAddress((void**)&w_l, sb_w_lo);
    cudaGetSymbolAddress((void**)&ow_h, sb_ow_hi);
    cudaGetSymbolAddress((void**)&ow_l, sb_ow_lo);
    cudaGetSymbolAddress((void**)&at_h, sb_at_hi);
    cudaGetSymbolAddress((void**)&at_l, sb_at_lo);
    cudaGetSymbolAddress((void**)&q_h, sbq_hi);
    cudaGetSymbolAddress((void**)&q_l, sbq_lo);
    cudaGetSymbolAddress((void**)&k_h, sbk_hi);
    cudaGetSymbolAddress((void**)&k_l, sbk_lo);
    cudaGetSymbolAddress((void**)&v_h, sbv_hi);
    cudaGetSymbolAddress((void**)&v_l, sbv_lo);

    const int gemm_smem = 2 * 4 * GSTG * (int)sizeof(__nv_bfloat16);
    cudaFuncSetAttribute(gemm_bf16split, cudaFuncAttributeMaxDynamicSharedMemorySize,
                         gemm_smem);
    cudaFuncSetAttribute(attn_mma_kernel, cudaFuncAttributeMaxDynamicSharedMemorySize,
                         ATT_SMEM_BYTES);

    SplitSegs segs;
    long n_hid = (long)T_TOK * HIDN / 4;
    long n_qw  = (long)HIDN * HIDN / 4;
    long n_kw  = (long)NKV * HD * HIDN / 4;
    segs.src[0] = (const float4*)hidden; segs.hi[0] = (__nv_bfloat162*)hid_h;
    segs.lo[0] = (__nv_bfloat162*)hid_l; segs.end[0] = n_hid;
    segs.src[1] = (const float4*)q_w;    segs.hi[1] = (__nv_bfloat162*)w_h;
    segs.lo[1] = (__nv_bfloat162*)w_l;   segs.end[1] = segs.end[0] + n_qw;
    segs.src[2] = (const float4*)k_w;
    segs.hi[2] = (__nv_bfloat162*)(w_h + (size_t)HIDN * HIDN);
    segs.lo[2] = (__nv_bfloat162*)(w_l + (size_t)HIDN * HIDN);
    segs.end[2] = segs.end[1] + n_kw;
    segs.src[3] = (const float4*)v_w;
    segs.hi[3] = (__nv_bfloat162*)(w_h + (size_t)HIDN * HIDN + (size_t)NKV * HD * HIDN);
    segs.lo[3] = (__nv_bfloat162*)(w_l + (size_t)HIDN * HIDN + (size_t)NKV * HD * HIDN);
    segs.end[3] = segs.end[2] + n_kw;
    segs.src[4] = (const float4*)o_w;    segs.hi[4] = (__nv_bfloat162*)ow_h;
    segs.lo[4] = (__nv_bfloat162*)ow_l;  segs.end[4] = segs.end[3] + n_qw;
    long total_thr = segs.end[4] / 4;
    split_all_kernel<<<(unsigned)((total_thr + 255) / 256), 256>>>(segs);

    // QKV projection: split-K=2 (z dimension), partials into g_qkv / g_qkv2
    gemm_bf16split<<<dim3(4096 / 128, T_TOK / 128, 2), 256, gemm_smem>>>(
        hid_h, hid_l, w_h, w_l, qkvp, qkv2p, T_TOK, 4096, HIDN / 2, HIDN);

    // RMSNorm + RoPE (reduces the two split-K partials on the fly)
    norm_rope_kernel<<<T_TOK, 256>>>(cosv, sinv, q_nw, k_nw);

    // Attention
    attn_mma_kernel<<<dim3(T_TOK / 64, NH), 256, ATT_SMEM_BYTES>>>(
        q_h, q_l, k_h, k_l, v_h, v_l, at_h, at_l);

    // Output projection (no split-K)
    gemm_bf16split<<<dim3(HIDN / 128, T_TOK / 128, 1), 256, gemm_smem>>>(
        at_h, at_l, ow_h, ow_l, (float*)d_out, (float*)d_out, T_TOK, HIDN, HIDN, HIDN);
}

// round 16
// speedup vs baseline: 1.0499x; 1.0499x over previous
#include <cuda_runtime.h>
#include <cuda_bf16.h>
#include <stdint.h>
#include <math.h>

// Problem constants
#define T_TOK 4096
#define HIDN  2048
#define NH    8
#define NKV   4
#define HD    256
#define SWIN  1024

// GEMM tiling (2-stage, 2 CTAs/SM)
#define GBK 32
#define GSTRIDE 40
#define GSTG (128 * GSTRIDE)

// Attention smem layout (bf16 element offsets)
#define DS   264
#define PSTR 72
#define ATT_QH 0
#define ATT_QL (64 * DS)
#define ATT_KH (2 * 64 * DS)
#define ATT_KL (3 * 64 * DS)
#define ATT_VH (4 * 64 * DS)
#define ATT_VL (5 * 64 * DS)
#define ATT_PH (6 * 64 * DS)
#define ATT_PL (ATT_PH + 64 * PSTR)
#define ATT_F  (ATT_PL + 64 * PSTR)
#define ATT_SMEM_BYTES (ATT_F * 2 + 512 * 4)

// Scratch (static device globals — allocation-free)
__device__ float g_qkv[T_TOK * 4096];   // cols 0-2047 q, 2048-3071 k, 3072-4095 v

__device__ __nv_bfloat16 sb_hid_hi[T_TOK * HIDN], sb_hid_lo[T_TOK * HIDN];
__device__ __nv_bfloat16 sb_w_hi[4096 * HIDN],    sb_w_lo[4096 * HIDN];  // [q;k;v]
__device__ __nv_bfloat16 sb_ow_hi[HIDN * HIDN],   sb_ow_lo[HIDN * HIDN];
__device__ __nv_bfloat16 sb_at_hi[T_TOK * HIDN],  sb_at_lo[T_TOK * HIDN];

__device__ __nv_bfloat16 sbq_hi[T_TOK * HIDN],     sbq_lo[T_TOK * HIDN];
__device__ __nv_bfloat16 sbk_hi[T_TOK * NKV * HD], sbk_lo[T_TOK * NKV * HD];
__device__ __nv_bfloat16 sbv_hi[T_TOK * NKV * HD], sbv_lo[T_TOK * NKV * HD];

// ---------------------------------------------------------------------------
#define LDSM4(R, addr) \
    asm volatile("ldmatrix.sync.aligned.m8n8.x4.shared.b16 {%0,%1,%2,%3}, [%4];" \
                 : "=r"((R)[0]), "=r"((R)[1]), "=r"((R)[2]), "=r"((R)[3]) : "r"(addr))

#define LDSM4T(R, addr) \
    asm volatile("ldmatrix.sync.aligned.m8n8.x4.trans.shared.b16 {%0,%1,%2,%3}, [%4];" \
                 : "=r"((R)[0]), "=r"((R)[1]), "=r"((R)[2]), "=r"((R)[3]) : "r"(addr))

#define MMA16816(Cacc, A, b0, b1) \
    asm volatile("mma.sync.aligned.m16n8k16.row.col.f32.bf16.bf16.f32 " \
                 "{%0,%1,%2,%3}, {%4,%5,%6,%7}, {%8,%9}, {%0,%1,%2,%3};" \
                 : "+f"((Cacc)[0]), "+f"((Cacc)[1]), "+f"((Cacc)[2]), "+f"((Cacc)[3]) \
                 : "r"((A)[0]), "r"((A)[1]), "r"((A)[2]), "r"((A)[3]), "r"(b0), "r"(b1))

#define CPA16(dst, src) \
    asm volatile("cp.async.cg.shared.global [%0], [%1], 16;" :: "r"(dst), "l"(src))

__device__ __forceinline__ unsigned int smem_u32(const void* p) {
    return (unsigned int)__cvta_generic_to_shared(p);
}

// ---------------------------------------------------------------------------
// Fused split: all 5 tensors in one launch, 4 float4s per thread (MLP=4).
// ---------------------------------------------------------------------------
struct SplitSegs {
    const float4* src[5];
    __nv_bfloat162* hi[5];
    __nv_bfloat162* lo[5];
    long end[5];
};

__global__ __launch_bounds__(256) void split_all_kernel(SplitSegs segs)
{
    long base = ((long)blockIdx.x * blockDim.x + threadIdx.x) * 4;
    if (base >= segs.end[4]) return;
    int s = 0;
    while (base >= segs.end[s]) ++s;
    long start = (s == 0) ? 0 : segs.end[s - 1];
    long loc = base - start;
    const float4* src = segs.src[s] + loc;
    __nv_bfloat162* hi = segs.hi[s] + 2 * loc;
    __nv_bfloat162* lo = segs.lo[s] + 2 * loc;
#pragma unroll
    for (int j = 0; j < 4; ++j) {
        float4 v = src[j];
        __nv_bfloat16 h0 = __float2bfloat16_rn(v.x);
        __nv_bfloat16 h1 = __float2bfloat16_rn(v.y);
        __nv_bfloat16 h2 = __float2bfloat16_rn(v.z);
        __nv_bfloat16 h3 = __float2bfloat16_rn(v.w);
        hi[2 * j]     = __halves2bfloat162(h0, h1);
        hi[2 * j + 1] = __halves2bfloat162(h2, h3);
        lo[2 * j]     = __halves2bfloat162(
            __float2bfloat16_rn(v.x - __bfloat162float(h0)),
            __float2bfloat16_rn(v.y - __bfloat162float(h1)));
        lo[2 * j + 1] = __halves2bfloat162(
            __float2bfloat16_rn(v.z - __bfloat162float(h2)),
            __float2bfloat16_rn(v.w - __bfloat162float(h3)));
    }
}

// ---------------------------------------------------------------------------
// Split-bf16 tensor-core NT GEMM, 2-stage cp.async, 2 CTAs/SM.
// Single __syncthreads per K-iteration: wait -> sync -> issue -> compute.
// ---------------------------------------------------------------------------
__global__ __launch_bounds__(256, 2) void gemm_bf16split(
    const __nv_bfloat16* __restrict__ Ah, const __nv_bfloat16* __restrict__ Al,
    const __nv_bfloat16* __restrict__ Bh, const __nv_bfloat16* __restrict__ Bl,
    float* __restrict__ C, int M, int N, int K)
{
    extern __shared__ __nv_bfloat16 sm[];
    const int tid = threadIdx.x;
    const int bm = blockIdx.y * 128, bn = blockIdx.x * 128;
    const int lane = tid & 31, wid = tid >> 5;
    const int wm = wid & 3, wn = wid >> 2;

#define GEMM_ISSUE(buf, k0)                                                        \
    {                                                                              \
        __nv_bfloat16* base = sm + (buf) * 4 * GSTG;                               \
        _Pragma("unroll")                                                          \
        for (int half = 0; half < 2; ++half) {                                     \
            int c = tid + half * 256;                                              \
            int row = c >> 2, cc = c & 3;                                          \
            unsigned int sA = smem_u32(base + row * GSTRIDE + cc * 8);             \
            const __nv_bfloat16* gAh = Ah + (size_t)(bm + row) * K + (k0) + cc*8;  \
            const __nv_bfloat16* gAl = Al + (size_t)(bm + row) * K + (k0) + cc*8;  \
            const __nv_bfloat16* gBh = Bh + (size_t)(bn + row) * K + (k0) + cc*8;  \
            const __nv_bfloat16* gBl = Bl + (size_t)(bn + row) * K + (k0) + cc*8;  \
            CPA16(sA, gAh);                                                        \
            CPA16(sA + GSTG * 2, gAl);                                             \
            CPA16(sA + GSTG * 4, gBh);                                             \
            CPA16(sA + GSTG * 6, gBl);                                             \
        }                                                                          \
        asm volatile("cp.async.commit_group;");                                    \
    }

    float acc[16][4];
#pragma unroll
    for (int t = 0; t < 16; ++t)
#pragma unroll
        for (int j = 0; j < 4; ++j) acc[t][j] = 0.f;

    GEMM_ISSUE(0, 0);

    const int iters = K / GBK;
    for (int it = 0; it < iters; ++it) {
        asm volatile("cp.async.wait_group 0;");
        __syncthreads();
        if (it + 1 < iters)
            GEMM_ISSUE((it + 1) & 1, (it + 1) * GBK);

        const __nv_bfloat16* st = sm + (it & 1) * 4 * GSTG;
#pragma unroll
        for (int ks = 0; ks < 2; ++ks) {
            unsigned int ah[2][4], al[2][4];
#pragma unroll
            for (int mt = 0; mt < 2; ++mt) {
                int row = wm * 32 + mt * 16 + (lane & 15);
                int col = ks * 16 + (lane >> 4) * 8;
                unsigned int ad = smem_u32(st + row * GSTRIDE + col);
                LDSM4(ah[mt], ad);
                LDSM4(al[mt], ad + GSTG * 2);
            }
#pragma unroll
            for (int p = 0; p < 4; ++p) {
                int r = lane & 7, g = lane >> 3;
                int nrow = wn * 64 + p * 16 + ((g >> 1) & 1) * 8 + r;
                int col = ks * 16 + (g & 1) * 8;
                unsigned int bd = smem_u32(st + 2 * GSTG + nrow * GSTRIDE + col);
                unsigned int bh[4], bl[4];
                LDSM4(bh, bd);
                LDSM4(bl, bd + GSTG * 2);
#pragma unroll
                for (int mt = 0; mt < 2; ++mt)
#pragma unroll
                    for (int o = 0; o < 4; o += 2)
                        MMA16816(acc[mt * 8 + p * 2 + (o >> 1)],
                                 ah[mt], bh[o], bh[o + 1]);
#pragma unroll
                for (int mt = 0; mt < 2; ++mt)
#pragma unroll
                    for (int o = 0; o < 4; o += 2)
                        MMA16816(acc[mt * 8 + p * 2 + (o >> 1)],
                                 ah[mt], bl[o], bl[o + 1]);
#pragma unroll
                for (int mt = 0; mt < 2; ++mt)
#pragma unroll
                    for (int o = 0; o < 4; o += 2)
                        MMA16816(acc[mt * 8 + p * 2 + (o >> 1)],
                                 al[mt], bh[o], bh[o + 1]);
            }
        }
    }

#pragma unroll
    for (int mt = 0; mt < 2; ++mt)
#pragma unroll
        for (int nt = 0; nt < 8; ++nt) {
            float* cc = acc[mt * 8 + nt];
            int r = bm + wm * 32 + mt * 16 + (lane >> 2);
            int cl = bn + wn * 64 + nt * 8 + (lane & 3) * 2;
            *(float2*)&C[(size_t)r * N + cl]       = make_float2(cc[0], cc[1]);
            *(float2*)&C[(size_t)(r + 8) * N + cl] = make_float2(cc[2], cc[3]);
        }
#undef GEMM_ISSUE
}

// ---------------------------------------------------------------------------
// RMSNorm (+weight) + RoPE, warp-per-role (reads fused g_qkv).
// ---------------------------------------------------------------------------
__device__ __forceinline__ void store_hl4(__nv_bfloat16* dh, __nv_bfloat16* dl,
                                          size_t off, float4 v)
{
    __nv_bfloat16 h0 = __float2bfloat16_rn(v.x), h1 = __float2bfloat16_rn(v.y);
    __nv_bfloat16 h2 = __float2bfloat16_rn(v.z), h3 = __float2bfloat16_rn(v.w);
    union { __nv_bfloat162 b[2]; uint2 u; } ph, pl;
    ph.b[0] = __halves2bfloat162(h0, h1);
    ph.b[1] = __halves2bfloat162(h2, h3);
    pl.b[0] = __halves2bfloat162(__float2bfloat16_rn(v.x - __bfloat162float(h0)),
                                 __float2bfloat16_rn(v.y - __bfloat162float(h1)));
    pl.b[1] = __halves2bfloat162(__float2bfloat16_rn(v.z - __bfloat162float(h2)),
                                 __float2bfloat16_rn(v.w - __bfloat162float(h3)));
    *(uint2*)(dh + off) = ph.u;
    *(uint2*)(dl + off) = pl.u;
}

__global__ __launch_bounds__(256) void norm_rope_kernel(
    const float* __restrict__ cosv, const float* __restrict__ sinv,
    const float* __restrict__ q_nw, const float* __restrict__ k_nw)
{
    const int t = blockIdx.x;
    const int wid = threadIdx.x >> 5, lane = threadIdx.x & 31;
    const int cA = lane * 4, cB = 128 + lane * 4;

#pragma unroll
    for (int rr = 0; rr < 2; ++rr) {
        const int role = wid * 2 + rr;
        const float* src;
        const float* w = nullptr;
        bool rope = true;
        __nv_bfloat16 *dh, *dl;
        size_t doff;
        if (role < 8) {
            src = g_qkv + (size_t)t * 4096 + role * HD; w = q_nw;
            dh = sbq_hi; dl = sbq_lo; doff = (size_t)t * HIDN + role * HD;
        } else if (role < 12) {
            src = g_qkv + (size_t)t * 4096 + 2048 + (role - 8) * HD; w = k_nw;
            dh = sbk_hi; dl = sbk_lo; doff = (size_t)t * 1024 + (role - 8) * HD;
        } else {
            src = g_qkv + (size_t)t * 4096 + 3072 + (role - 12) * HD; rope = false;
            dh = sbv_hi; dl = sbv_lo; doff = (size_t)t * 1024 + (role - 12) * HD;
        }

        float4 a = *(const float4*)(src + cA);
        float4 b = *(const float4*)(src + cB);
        float ss = a.x*a.x + a.y*a.y + a.z*a.z + a.w*a.w
                 + b.x*b.x + b.y*b.y + b.z*b.z + b.w*b.w;
#pragma unroll
        for (int o = 16; o >= 1; o >>= 1) ss += __shfl_xor_sync(0xffffffffu, ss, o);
        float rn = rsqrtf(ss * (1.f / HD) + 1e-6f);

        float4 ya, yb;
        if (w) {
            float4 wa = *(const float4*)(w + cA);
            float4 wb = *(const float4*)(w + cB);
            ya = make_float4(a.x*rn*wa.x, a.y*rn*wa.y, a.z*rn*wa.z, a.w*rn*wa.w);
            yb = make_float4(b.x*rn*wb.x, b.y*rn*wb.y, b.z*rn*wb.z, b.w*rn*wb.w);
        } else {
            ya = make_float4(a.x*rn, a.y*rn, a.z*rn, a.w*rn);
            yb = make_float4(b.x*rn, b.y*rn, b.z*rn, b.w*rn);
        }

        float4 oa = ya, ob = yb;
        if (rope) {
            const float* cp = cosv + (size_t)t * HD;
            const float* sp = sinv + (size_t)t * HD;
            float4 ca = *(const float4*)(cp + cA), cb = *(const float4*)(cp + cB);
            float4 sa = *(const float4*)(sp + cA), sb = *(const float4*)(sp + cB);
            oa = make_float4(ya.x*ca.x - yb.x*sa.x, ya.y*ca.y - yb.y*sa.y,
                             ya.z*ca.z - yb.z*sa.z, ya.w*ca.w - yb.w*sa.w);
            ob = make_float4(yb.x*cb.x + ya.x*sb.x, yb.y*cb.y + ya.y*sb.y,
                             yb.z*cb.z + ya.z*sb.z, yb.w*cb.w + ya.w*sb.w);
        }
        store_hl4(dh, dl, doff + cA, oa);
        store_hl4(dh, dl, doff + cB, ob);
    }
}

// ---------------------------------------------------------------------------
// Sliding-window flash attention (best-measured variant, 256 threads):
// pipelined K/V loads + ping-pong softmax stats.
// ---------------------------------------------------------------------------
__global__ __launch_bounds__(256) void attn_mma_kernel(
    const __nv_bfloat16* __restrict__ Qh, const __nv_bfloat16* __restrict__ Ql,
    const __nv_bfloat16* __restrict__ Kh, const __nv_bfloat16* __restrict__ Kl,
    const __nv_bfloat16* __restrict__ Vh, const __nv_bfloat16* __restrict__ Vl,
    __nv_bfloat16* __restrict__ Oh, __nv_bfloat16* __restrict__ Ol)
{
    extern __shared__ __nv_bfloat16 sm[];
    float* fb   = (float*)(sm + ATT_F);
    float* pmax = fb + 256;
    float* psum = fb + 384;

    const int qb = blockIdx.x, h = blockIdx.y;
    const int q0 = qb * 64;
    const int kvh = h >> 1;
    const int tid = threadIdx.x;
    const int lane = tid & 31, wid = tid >> 5;
    const int wm = wid & 3, wn = wid >> 2;
    const int wm2 = wid & 1, wn2 = wid >> 1;

    if (tid < 64) { fb[tid] = -1e30f; fb[128 + tid] = 0.f; }

#define ISSUE_K(k0)                                                            \
    {                                                                          \
        for (int i = tid; i < 2048; i += 256) {                                \
            int r = i >> 5, c = (i & 31) * 8;                                  \
            size_t g = (size_t)((k0) + r) * (NKV * HD) + kvh * HD + c;         \
            CPA16(smem_u32(sm + ATT_KH + r * DS + c), Kh + g);                 \
            CPA16(smem_u32(sm + ATT_KL + r * DS + c), Kl + g);                 \
        }                                                                      \
        asm volatile("cp.async.commit_group;");                                \
    }
#define ISSUE_V(k0)                                                            \
    {                                                                          \
        for (int i = tid; i < 2048; i += 256) {                                \
            int r = i >> 5, c = (i & 31) * 8;                                  \
            size_t g = (size_t)((k0) + r) * (NKV * HD) + kvh * HD + c;         \
            CPA16(smem_u32(sm + ATT_VH + r * DS + c), Vh + g);                 \
            CPA16(smem_u32(sm + ATT_VL + r * DS + c), Vl + g);                 \
        }                                                                      \
        asm volatile("cp.async.commit_group;");                                \
    }

    for (int i = tid; i < 2048; i += 256) {
        int r = i >> 5, c = (i & 31) * 8;
        size_t g = (size_t)(q0 + r) * HIDN + h * HD + c;
        CPA16(smem_u32(sm + ATT_QH + r * DS + c), Qh + g);
        CPA16(smem_u32(sm + ATT_QL + r * DS + c), Ql + g);
    }
    asm volatile("cp.async.commit_group;");

    float o_acc[2][8][4];
#pragma unroll
    for (int mt = 0; mt < 2; ++mt)
#pragma unroll
        for (int nt = 0; nt < 8; ++nt)
#pragma unroll
            for (int e = 0; e < 4; ++e) o_acc[mt][nt][e] = 0.f;

    int jmin = q0 - (SWIN - 1); if (jmin < 0) jmin = 0;
    const int t0 = jmin >> 6;
    const int t1 = (q0 + 63) >> 6;
    const int ntiles = t1 - t0 + 1;

    ISSUE_K(t0 * 64);
    ISSUE_V(t0 * 64);
    asm volatile("cp.async.wait_group 1;");
    __syncthreads();

    for (int kt = t0; kt <= t1; ++kt) {
        const int k0 = kt * 64;
        const int pp = (kt - t0) & 1;
        float* m_old = fb + pp * 64;
        float* m_newp = fb + (pp ^ 1) * 64;
        float* l_old = fb + 128 + pp * 64;
        float* l_newp = fb + 128 + (pp ^ 1) * 64;

        // ---- Phase 1: S = Q K^T ----
        float sacc[4][4];
#pragma unroll
        for (int nt = 0; nt < 4; ++nt)
#pragma unroll
            for (int e = 0; e < 4; ++e) sacc[nt][e] = 0.f;

#pragma unroll 4
        for (int ks = 0; ks < 16; ++ks) {
            unsigned int ah[4], al[4];
            {
                int row = wm * 16 + (lane & 15);
                int col = ks * 16 + (lane >> 4) * 8;
                LDSM4(ah, smem_u32(sm + ATT_QH + row * DS + col));
                LDSM4(al, smem_u32(sm + ATT_QL + row * DS + col));
            }
            unsigned int bh[2][4], bl[2][4];
#pragma unroll
            for (int p = 0; p < 2; ++p) {
                int nrow = wn * 32 + p * 16 + ((lane >> 4) << 3) + (lane & 7);
                int col = ks * 16 + ((lane >> 3) & 1) * 8;
                LDSM4(bh[p], smem_u32(sm + ATT_KH + nrow * DS + col));
                LDSM4(bl[p], smem_u32(sm + ATT_KL + nrow * DS + col));
            }
#pragma unroll
            for (int p = 0; p < 2; ++p)
#pragma unroll
                for (int o = 0; o < 4; o += 2)
                    MMA16816(sacc[p * 2 + (o >> 1)], ah, bh[p][o], bh[p][o + 1]);
#pragma unroll
            for (int p = 0; p < 2; ++p)
#pragma unroll
                for (int o = 0; o < 4; o += 2)
                    MMA16816(sacc[p * 2 + (o >> 1)], ah, bl[p][o], bl[p][o + 1]);
#pragma unroll
            for (int p = 0; p < 2; ++p)
#pragma unroll
                for (int o = 0; o < 4; o += 2)
                    MMA16816(sacc[p * 2 + (o >> 1)], al, bh[p][o], bh[p][o + 1]);
        }

        // Mask
        const int r_lo = q0 + wm * 16 + (lane >> 2);
        const int r_hi = r_lo + 8;
#pragma unroll
        for (int nt = 0; nt < 4; ++nt) {
#pragma unroll
            for (int e = 0; e < 2; ++e) {
                int j = k0 + wn * 32 + nt * 8 + (lane & 3) * 2 + e;
                if (!(j <= r_lo && r_lo - j < SWIN)) sacc[nt][e] = -1e30f;
                if (!(j <= r_hi && r_hi - j < SWIN)) sacc[nt][e + 2] = -1e30f;
            }
        }

        float mx0 = -1e30f, mx1 = -1e30f;
#pragma unroll
        for (int nt = 0; nt < 4; ++nt) {
            mx0 = fmaxf(mx0, fmaxf(sacc[nt][0], sacc[nt][1]));
            mx1 = fmaxf(mx1, fmaxf(sacc[nt][2], sacc[nt][3]));
        }
        mx0 = fmaxf(mx0, __shfl_xor_sync(0xffffffffu, mx0, 1));
        mx0 = fmaxf(mx0, __shfl_xor_sync(0xffffffffu, mx0, 2));
        mx1 = fmaxf(mx1, __shfl_xor_sync(0xffffffffu, mx1, 1));
        mx1 = fmaxf(mx1, __shfl_xor_sync(0xffffffffu, mx1, 2));
        if ((lane & 3) == 0) {
            pmax[wn * 64 + wm * 16 + (lane >> 2)]     = mx0;
            pmax[wn * 64 + wm * 16 + 8 + (lane >> 2)] = mx1;
        }
        __syncthreads();

        if (kt < t1) ISSUE_K(k0 + 64);

        float mo_t = 0.f, mn_t = 0.f;
        if (tid < 64) {
            mo_t = m_old[tid];
            mn_t = fmaxf(mo_t, fmaxf(pmax[tid], pmax[64 + tid]));
            m_newp[tid] = mn_t;
        }
        {
            const int pr0 = wm * 16 + (lane >> 2);
            const int pr1 = pr0 + 8;
            float m0v = fmaxf(m_old[pr0], fmaxf(pmax[pr0], pmax[64 + pr0]));
            float m1v = fmaxf(m_old[pr1], fmaxf(pmax[pr1], pmax[64 + pr1]));
            float s0 = 0.f, s1 = 0.f;
#pragma unroll
            for (int nt = 0; nt < 4; ++nt) {
                float p00 = (sacc[nt][0] > -1e29f) ? __expf(sacc[nt][0] - m0v) : 0.f;
                float p01 = (sacc[nt][1] > -1e29f) ? __expf(sacc[nt][1] - m0v) : 0.f;
                float p10 = (sacc[nt][2] > -1e29f) ? __expf(sacc[nt][2] - m1v) : 0.f;
                float p11 = (sacc[nt][3] > -1e29f) ? __expf(sacc[nt][3] - m1v) : 0.f;
                s0 += p00 + p01; s1 += p10 + p11;
                int colb = wn * 32 + nt * 8 + (lane & 3) * 2;
                __nv_bfloat16 h00 = __float2bfloat16_rn(p00);
                __nv_bfloat16 h01 = __float2bfloat16_rn(p01);
                __nv_bfloat16 h10 = __float2bfloat16_rn(p10);
                __nv_bfloat16 h11 = __float2bfloat16_rn(p11);
                *(__nv_bfloat162*)(sm + ATT_PH + pr0 * PSTR + colb) =
                    __halves2bfloat162(h00, h01);
                *(__nv_bfloat162*)(sm + ATT_PH + pr1 * PSTR + colb) =
                    __halves2bfloat162(h10, h11);
                *(__nv_bfloat162*)(sm + ATT_PL + pr0 * PSTR + colb) =
                    __halves2bfloat162(
                        __float2bfloat16_rn(p00 - __bfloat162float(h00)),
                        __float2bfloat16_rn(p01 - __bfloat162float(h01)));
                *(__nv_bfloat162*)(sm + ATT_PL + pr1 * PSTR + colb) =
                    __halves2bfloat162(
                        __float2bfloat16_rn(p10 - __bfloat162float(h10)),
                        __float2bfloat16_rn(p11 - __bfloat162float(h11)));
            }
            s0 += __shfl_xor_sync(0xffffffffu, s0, 1);
            s0 += __shfl_xor_sync(0xffffffffu, s0, 2);
            s1 += __shfl_xor_sync(0xffffffffu, s1, 1);
            s1 += __shfl_xor_sync(0xffffffffu, s1, 2);
            if ((lane & 3) == 0) {
                psum[wn * 64 + wm * 16 + (lane >> 2)]     = s0;
                psum[wn * 64 + wm * 16 + 8 + (lane >> 2)] = s1;
            }
        }

        // Rescale O while V(t) finishes loading
#pragma unroll
        for (int mt = 0; mt < 2; ++mt) {
            int r0 = wm2 * 32 + mt * 16 + (lane >> 2);
            int r1 = r0 + 8;
            float a0 = m_old[r0];
            float sL = __expf(a0 - fmaxf(a0, fmaxf(pmax[r0], pmax[64 + r0])));
            float a1 = m_old[r1];
            float sH = __expf(a1 - fmaxf(a1, fmaxf(pmax[r1], pmax[64 + r1])));
#pragma unroll
            for (int nt = 0; nt < 8; ++nt) {
                o_acc[mt][nt][0] *= sL; o_acc[mt][nt][1] *= sL;
                o_acc[mt][nt][2] *= sH; o_acc[mt][nt][3] *= sH;
            }
        }

        if (kt < t1) { asm volatile("cp.async.wait_group 1;"); }
        else         { asm volatile("cp.async.wait_group 0;"); }
        __syncthreads();

        if (tid < 64)
            l_newp[tid] = l_old[tid] * __expf(mo_t - mn_t)
                          + psum[tid] + psum[64 + tid];

        // ---- Phase 2: O += P V ----
#pragma unroll
        for (int ks2 = 0; ks2 < 4; ++ks2) {
            unsigned int aph[2][4], apl[2][4];
#pragma unroll
            for (int mt = 0; mt < 2; ++mt) {
                int row = wm2 * 32 + mt * 16 + (lane & 15);
                int col = ks2 * 16 + (lane >> 4) * 8;
                LDSM4(aph[mt], smem_u32(sm + ATT_PH + row * PSTR + col));
                LDSM4(apl[mt], smem_u32(sm + ATT_PL + row * PSTR + col));
            }
#pragma unroll
            for (int ng = 0; ng < 4; ++ng) {
                int vr = ks2 * 16 + ((lane >> 3) & 1) * 8 + (lane & 7);
                int vc = wn2 * 64 + ng * 16 + (lane >> 4) * 8;
                unsigned int bvh[4], bvl[4];
                LDSM4T(bvh, smem_u32(sm + ATT_VH + vr * DS + vc));
                LDSM4T(bvl, smem_u32(sm + ATT_VL + vr * DS + vc));
#pragma unroll
                for (int mt = 0; mt < 2; ++mt)
#pragma unroll
                    for (int o = 0; o < 4; o += 2)
                        MMA16816(o_acc[mt][ng * 2 + (o >> 1)],
                                 aph[mt], bvh[o], bvh[o + 1]);
#pragma unroll
                for (int mt = 0; mt < 2; ++mt)
#pragma unroll
                    for (int o = 0; o < 4; o += 2)
                        MMA16816(o_acc[mt][ng * 2 + (o >> 1)],
                                 aph[mt], bvl[o], bvl[o + 1]);
#pragma unroll
                for (int mt = 0; mt < 2; ++mt)
#pragma unroll
                    for (int o = 0; o < 4; o += 2)
                        MMA16816(o_acc[mt][ng * 2 + (o >> 1)],
                                 apl[mt], bvh[o], bvh[o + 1]);
            }
        }
        __syncthreads();

        if (kt < t1) {
            ISSUE_V(k0 + 64);
            asm volatile("cp.async.wait_group 1;");
            __syncthreads();
        }
    }

    // Epilogue
    float* l_fin = fb + 128 + (ntiles & 1) * 64;
#pragma unroll
    for (int mt = 0; mt < 2; ++mt) {
        int rL = wm2 * 32 + mt * 16 + (lane >> 2);
        int rH = rL + 8;
        float invL = 1.f / l_fin[rL];
        float invH = 1.f / l_fin[rH];
#pragma unroll
        for (int nt = 0; nt < 8; ++nt) {
            int col = wn2 * 64 + nt * 8 + (lane & 3) * 2;
            size_t gL = (size_t)(q0 + rL) * HIDN + h * HD + col;
            size_t gH = (size_t)(q0 + rH) * HIDN + h * HD + col;
            float v0 = o_acc[mt][nt][0] * invL, v1 = o_acc[mt][nt][1] * invL;
            float v2 = o_acc[mt][nt][2] * invH, v3 = o_acc[mt][nt][3] * invH;
            __nv_bfloat16 h0 = __float2bfloat16_rn(v0), h1 = __float2bfloat16_rn(v1);
            __nv_bfloat16 h2 = __float2bfloat16_rn(v2), h3 = __float2bfloat16_rn(v3);
            *(__nv_bfloat162*)(Oh + gL) = __halves2bfloat162(h0, h1);
            *(__nv_bfloat162*)(Oh + gH) = __halves2bfloat162(h2, h3);
            *(__nv_bfloat162*)(Ol + gL) = __halves2bfloat162(
                __float2bfloat16_rn(v0 - __bfloat162float(h0)),
                __float2bfloat16_rn(v1 - __bfloat162float(h1)));
            *(__nv_bfloat162*)(Ol + gH) = __halves2bfloat162(
                __float2bfloat16_rn(v2 - __bfloat162float(h2)),
                __float2bfloat16_rn(v3 - __bfloat162float(h3)));
        }
    }
#undef ISSUE_K
#undef ISSUE_V
}

// ---------------------------------------------------------------------------
extern "C" void kernel_launch(void* const* d_in, const int* in_sizes, int n_in,
                              void* d_out, int out_size)
{
    const float* hidden = (const float*)d_in[0];
    const float* cosv   = (const float*)d_in[1];
    const float* sinv   = (const float*)d_in[2];
    const float* q_w    = (const float*)d_in[3];
    const float* k_w    = (const float*)d_in[4];
    const float* v_w    = (const float*)d_in[5];
    const float* o_w    = (const float*)d_in[6];
    const float* q_nw   = (const float*)d_in[7];
    const float* k_nw   = (const float*)d_in[8];

    float* qkvp;
    cudaGetSymbolAddress((void**)&qkvp, g_qkv);

    __nv_bfloat16 *hid_h, *hid_l, *w_h, *w_l, *ow_h, *ow_l, *at_h, *at_l,
                  *q_h, *q_l, *k_h, *k_l, *v_h, *v_l;
    cudaGetSymbolAddress((void**)&hid_h, sb_hid_hi);
    cudaGetSymbolAddress((void**)&hid_l, sb_hid_lo);
    cudaGetSymbolAddress((void**)&w_h, sb_w_hi);
    cudaGetSymbolAddress((void**)&w_l, sb_w_lo);
    cudaGetSymbolAddress((void**)&ow_h, sb_ow_hi);
    cudaGetSymbolAddress((void**)&ow_l, sb_ow_lo);
    cudaGetSymbolAddress((void**)&at_h, sb_at_hi);
    cudaGetSymbolAddress((void**)&at_l, sb_at_lo);
    cudaGetSymbolAddress((void**)&q_h, sbq_hi);
    cudaGetSymbolAddress((void**)&q_l, sbq_lo);
    cudaGetSymbolAddress((void**)&k_h, sbk_hi);
    cudaGetSymbolAddress((void**)&k_l, sbk_lo);
    cudaGetSymbolAddress((void**)&v_h, sbv_hi);
    cudaGetSymbolAddress((void**)&v_l, sbv_lo);

    const int gemm_smem = 2 * 4 * GSTG * (int)sizeof(__nv_bfloat16);
    cudaFuncSetAttribute(gemm_bf16split, cudaFuncAttributeMaxDynamicSharedMemorySize,
                         gemm_smem);
    cudaFuncSetAttribute(attn_mma_kernel, cudaFuncAttributeMaxDynamicSharedMemorySize,
                         ATT_SMEM_BYTES);

    SplitSegs segs;
    long n_hid = (long)T_TOK * HIDN / 4;
    long n_qw  = (long)HIDN * HIDN / 4;
    long n_kw  = (long)NKV * HD * HIDN / 4;
    segs.src[0] = (const float4*)hidden; segs.hi[0] = (__nv_bfloat162*)hid_h;
    segs.lo[0] = (__nv_bfloat162*)hid_l; segs.end[0] = n_hid;
    segs.src[1] = (const float4*)q_w;    segs.hi[1] = (__nv_bfloat162*)w_h;
    segs.lo[1] = (__nv_bfloat162*)w_l;   segs.end[1] = segs.end[0] + n_qw;
    segs.src[2] = (const float4*)k_w;
    segs.hi[2] = (__nv_bfloat162*)(w_h + (size_t)HIDN * HIDN);
    segs.lo[2] = (__nv_bfloat162*)(w_l + (size_t)HIDN * HIDN);
    segs.end[2] = segs.end[1] + n_kw;
    segs.src[3] = (const float4*)v_w;
    segs.hi[3] = (__nv_bfloat162*)(w_h + (size_t)HIDN * HIDN + (size_t)NKV * HD * HIDN);
    segs.lo[3] = (__nv_bfloat162*)(w_l + (size_t)HIDN * HIDN + (size_t)NKV * HD * HIDN);
    segs.end[3] = segs.end[2] + n_kw;
    segs.src[4] = (const float4*)o_w;    segs.hi[4] = (__nv_bfloat162*)ow_h;
    segs.lo[4] = (__nv_bfloat162*)ow_l;  segs.end[4] = segs.end[3] + n_qw;
    long total_thr = segs.end[4] / 4;
    split_all_kernel<<<(unsigned)((total_thr + 255) / 256), 256>>>(segs);

    gemm_bf16split<<<dim3(4096 / 128, T_TOK / 128), 256, gemm_smem>>>(
        hid_h, hid_l, w_h, w_l, qkvp, T_TOK, 4096, HIDN);

    norm_rope_kernel<<<T_TOK, 256>>>(cosv, sinv, q_nw, k_nw);

    attn_mma_kernel<<<dim3(T_TOK / 64, NH), 256, ATT_SMEM_BYTES>>>(
        q_h, q_l, k_h, k_l, v_h, v_l, at_h, at_l);

    gemm_bf16split<<<dim3(HIDN / 128, T_TOK / 128), 256, gemm_smem>>>(
        at_h, at_l, ow_h, ow_l, (float*)d_out, T_TOK, HIDN, HIDN);
}

// round 17
// speedup vs baseline: 1.0563x; 1.0061x over previous
#include <cuda_runtime.h>
#include <cuda_bf16.h>
#include <stdint.h>
#include <math.h>

// Problem constants
#define T_TOK 4096
#define HIDN  2048
#define NH    8
#define NKV   4
#define HD    256
#define SWIN  1024

// GEMM tiling (2-stage, 2 CTAs/SM)
#define GBK 32
#define GSTRIDE 40
#define GSTG (128 * GSTRIDE)

// Attention smem layout (bf16 element offsets)
#define DS   264
#define PSTR 72
#define ATT_QH 0
#define ATT_QL (64 * DS)
#define ATT_KH (2 * 64 * DS)
#define ATT_KL (3 * 64 * DS)
#define ATT_VH (4 * 64 * DS)
#define ATT_VL (5 * 64 * DS)
#define ATT_PH (6 * 64 * DS)
#define ATT_PL (ATT_PH + 64 * PSTR)
#define ATT_F  (ATT_PL + 64 * PSTR)
#define ATT_SMEM_BYTES (ATT_F * 2 + 512 * 4)

// Scratch (static device globals — allocation-free)
__device__ float g_qkv[T_TOK * 4096];   // cols 0-2047 q, 2048-3071 k, 3072-4095 v

__device__ __nv_bfloat16 sb_hid_hi[T_TOK * HIDN], sb_hid_lo[T_TOK * HIDN];
__device__ __nv_bfloat16 sb_w_hi[4096 * HIDN],    sb_w_lo[4096 * HIDN];  // [q;k;v]
__device__ __nv_bfloat16 sb_ow_hi[HIDN * HIDN],   sb_ow_lo[HIDN * HIDN];
__device__ __nv_bfloat16 sb_at_hi[T_TOK * HIDN],  sb_at_lo[T_TOK * HIDN];

__device__ __nv_bfloat16 sbq_hi[T_TOK * HIDN],     sbq_lo[T_TOK * HIDN];
__device__ __nv_bfloat16 sbk_hi[T_TOK * NKV * HD], sbk_lo[T_TOK * NKV * HD];
__device__ __nv_bfloat16 sbv_hi[T_TOK * NKV * HD], sbv_lo[T_TOK * NKV * HD];

// ---------------------------------------------------------------------------
#define LDSM4(R, addr) \
    asm volatile("ldmatrix.sync.aligned.m8n8.x4.shared.b16 {%0,%1,%2,%3}, [%4];" \
                 : "=r"((R)[0]), "=r"((R)[1]), "=r"((R)[2]), "=r"((R)[3]) : "r"(addr))

#define LDSM4T(R, addr) \
    asm volatile("ldmatrix.sync.aligned.m8n8.x4.trans.shared.b16 {%0,%1,%2,%3}, [%4];" \
                 : "=r"((R)[0]), "=r"((R)[1]), "=r"((R)[2]), "=r"((R)[3]) : "r"(addr))

#define MMA16816(Cacc, A, b0, b1) \
    asm volatile("mma.sync.aligned.m16n8k16.row.col.f32.bf16.bf16.f32 " \
                 "{%0,%1,%2,%3}, {%4,%5,%6,%7}, {%8,%9}, {%0,%1,%2,%3};" \
                 : "+f"((Cacc)[0]), "+f"((Cacc)[1]), "+f"((Cacc)[2]), "+f"((Cacc)[3]) \
                 : "r"((A)[0]), "r"((A)[1]), "r"((A)[2]), "r"((A)[3]), "r"(b0), "r"(b1))

#define CPA16(dst, src) \
    asm volatile("cp.async.cg.shared.global [%0], [%1], 16;" :: "r"(dst), "l"(src))

__device__ __forceinline__ unsigned int smem_u32(const void* p) {
    return (unsigned int)__cvta_generic_to_shared(p);
}

// ---------------------------------------------------------------------------
// Fused split: all 5 tensors in one launch, 4 float4s per thread (MLP=4).
// ---------------------------------------------------------------------------
struct SplitSegs {
    const float4* src[5];
    __nv_bfloat162* hi[5];
    __nv_bfloat162* lo[5];
    long end[5];
};

__global__ __launch_bounds__(256) void split_all_kernel(SplitSegs segs)
{
    long base = ((long)blockIdx.x * blockDim.x + threadIdx.x) * 4;
    if (base >= segs.end[4]) return;
    int s = 0;
    while (base >= segs.end[s]) ++s;
    long start = (s == 0) ? 0 : segs.end[s - 1];
    long loc = base - start;
    const float4* src = segs.src[s] + loc;
    __nv_bfloat162* hi = segs.hi[s] + 2 * loc;
    __nv_bfloat162* lo = segs.lo[s] + 2 * loc;
#pragma unroll
    for (int j = 0; j < 4; ++j) {
        float4 v = src[j];
        __nv_bfloat16 h0 = __float2bfloat16_rn(v.x);
        __nv_bfloat16 h1 = __float2bfloat16_rn(v.y);
        __nv_bfloat16 h2 = __float2bfloat16_rn(v.z);
        __nv_bfloat16 h3 = __float2bfloat16_rn(v.w);
        hi[2 * j]     = __halves2bfloat162(h0, h1);
        hi[2 * j + 1] = __halves2bfloat162(h2, h3);
        lo[2 * j]     = __halves2bfloat162(
            __float2bfloat16_rn(v.x - __bfloat162float(h0)),
            __float2bfloat16_rn(v.y - __bfloat162float(h1)));
        lo[2 * j + 1] = __halves2bfloat162(
            __float2bfloat16_rn(v.z - __bfloat162float(h2)),
            __float2bfloat16_rn(v.w - __bfloat162float(h3)));
    }
}

// ---------------------------------------------------------------------------
// Split-bf16 tensor-core NT GEMM, 2-stage cp.async, 2 CTAs/SM.
// Single __syncthreads per K-iteration: wait -> sync -> issue -> compute.
// ---------------------------------------------------------------------------
__global__ __launch_bounds__(256, 2) void gemm_bf16split(
    const __nv_bfloat16* __restrict__ Ah, const __nv_bfloat16* __restrict__ Al,
    const __nv_bfloat16* __restrict__ Bh, const __nv_bfloat16* __restrict__ Bl,
    float* __restrict__ C, int M, int N, int K)
{
    extern __shared__ __nv_bfloat16 sm[];
    const int tid = threadIdx.x;
    const int bm = blockIdx.y * 128, bn = blockIdx.x * 128;
    const int lane = tid & 31, wid = tid >> 5;
    const int wm = wid & 3, wn = wid >> 2;

#define GEMM_ISSUE(buf, k0)                                                        \
    {                                                                              \
        __nv_bfloat16* base = sm + (buf) * 4 * GSTG;                               \
        _Pragma("unroll")                                                          \
        for (int half = 0; half < 2; ++half) {                                     \
            int c = tid + half * 256;                                              \
            int row = c >> 2, cc = c & 3;                                          \
            unsigned int sA = smem_u32(base + row * GSTRIDE + cc * 8);             \
            const __nv_bfloat16* gAh = Ah + (size_t)(bm + row) * K + (k0) + cc*8;  \
            const __nv_bfloat16* gAl = Al + (size_t)(bm + row) * K + (k0) + cc*8;  \
            const __nv_bfloat16* gBh = Bh + (size_t)(bn + row) * K + (k0) + cc*8;  \
            const __nv_bfloat16* gBl = Bl + (size_t)(bn + row) * K + (k0) + cc*8;  \
            CPA16(sA, gAh);                                                        \
            CPA16(sA + GSTG * 2, gAl);                                             \
            CPA16(sA + GSTG * 4, gBh);                                             \
            CPA16(sA + GSTG * 6, gBl);                                             \
        }                                                                          \
        asm volatile("cp.async.commit_group;");                                    \
    }

    float acc[16][4];
#pragma unroll
    for (int t = 0; t < 16; ++t)
#pragma unroll
        for (int j = 0; j < 4; ++j) acc[t][j] = 0.f;

    GEMM_ISSUE(0, 0);

    const int iters = K / GBK;
    for (int it = 0; it < iters; ++it) {
        asm volatile("cp.async.wait_group 0;");
        __syncthreads();
        if (it + 1 < iters)
            GEMM_ISSUE((it + 1) & 1, (it + 1) * GBK);

        const __nv_bfloat16* st = sm + (it & 1) * 4 * GSTG;
#pragma unroll
        for (int ks = 0; ks < 2; ++ks) {
            unsigned int ah[2][4], al[2][4];
#pragma unroll
            for (int mt = 0; mt < 2; ++mt) {
                int row = wm * 32 + mt * 16 + (lane & 15);
                int col = ks * 16 + (lane >> 4) * 8;
                unsigned int ad = smem_u32(st + row * GSTRIDE + col);
                LDSM4(ah[mt], ad);
                LDSM4(al[mt], ad + GSTG * 2);
            }
#pragma unroll
            for (int p = 0; p < 4; ++p) {
                int r = lane & 7, g = lane >> 3;
                int nrow = wn * 64 + p * 16 + ((g >> 1) & 1) * 8 + r;
                int col = ks * 16 + (g & 1) * 8;
                unsigned int bd = smem_u32(st + 2 * GSTG + nrow * GSTRIDE + col);
                unsigned int bh[4], bl[4];
                LDSM4(bh, bd);
                LDSM4(bl, bd + GSTG * 2);
#pragma unroll
                for (int mt = 0; mt < 2; ++mt)
#pragma unroll
                    for (int o = 0; o < 4; o += 2)
                        MMA16816(acc[mt * 8 + p * 2 + (o >> 1)],
                                 ah[mt], bh[o], bh[o + 1]);
#pragma unroll
                for (int mt = 0; mt < 2; ++mt)
#pragma unroll
                    for (int o = 0; o < 4; o += 2)
                        MMA16816(acc[mt * 8 + p * 2 + (o >> 1)],
                                 ah[mt], bl[o], bl[o + 1]);
#pragma unroll
                for (int mt = 0; mt < 2; ++mt)
#pragma unroll
                    for (int o = 0; o < 4; o += 2)
                        MMA16816(acc[mt * 8 + p * 2 + (o >> 1)],
                                 al[mt], bh[o], bh[o + 1]);
            }
        }
    }

#pragma unroll
    for (int mt = 0; mt < 2; ++mt)
#pragma unroll
        for (int nt = 0; nt < 8; ++nt) {
            float* cc = acc[mt * 8 + nt];
            int r = bm + wm * 32 + mt * 16 + (lane >> 2);
            int cl = bn + wn * 64 + nt * 8 + (lane & 3) * 2;
            *(float2*)&C[(size_t)r * N + cl]       = make_float2(cc[0], cc[1]);
            *(float2*)&C[(size_t)(r + 8) * N + cl] = make_float2(cc[2], cc[3]);
        }
#undef GEMM_ISSUE
}

// ---------------------------------------------------------------------------
// RMSNorm (+weight) + RoPE, warp-per-role (reads fused g_qkv).
// ---------------------------------------------------------------------------
__device__ __forceinline__ void store_hl4(__nv_bfloat16* dh, __nv_bfloat16* dl,
                                          size_t off, float4 v)
{
    __nv_bfloat16 h0 = __float2bfloat16_rn(v.x), h1 = __float2bfloat16_rn(v.y);
    __nv_bfloat16 h2 = __float2bfloat16_rn(v.z), h3 = __float2bfloat16_rn(v.w);
    union { __nv_bfloat162 b[2]; uint2 u; } ph, pl;
    ph.b[0] = __halves2bfloat162(h0, h1);
    ph.b[1] = __halves2bfloat162(h2, h3);
    pl.b[0] = __halves2bfloat162(__float2bfloat16_rn(v.x - __bfloat162float(h0)),
                                 __float2bfloat16_rn(v.y - __bfloat162float(h1)));
    pl.b[1] = __halves2bfloat162(__float2bfloat16_rn(v.z - __bfloat162float(h2)),
                                 __float2bfloat16_rn(v.w - __bfloat162float(h3)));
    *(uint2*)(dh + off) = ph.u;
    *(uint2*)(dl + off) = pl.u;
}

__global__ __launch_bounds__(256) void norm_rope_kernel(
    const float* __restrict__ cosv, const float* __restrict__ sinv,
    const float* __restrict__ q_nw, const float* __restrict__ k_nw)
{
    const int t = blockIdx.x;
    const int wid = threadIdx.x >> 5, lane = threadIdx.x & 31;
    const int cA = lane * 4, cB = 128 + lane * 4;

#pragma unroll
    for (int rr = 0; rr < 2; ++rr) {
        const int role = wid * 2 + rr;
        const float* src;
        const float* w = nullptr;
        bool rope = true;
        __nv_bfloat16 *dh, *dl;
        size_t doff;
        if (role < 8) {
            src = g_qkv + (size_t)t * 4096 + role * HD; w = q_nw;
            dh = sbq_hi; dl = sbq_lo; doff = (size_t)t * HIDN + role * HD;
        } else if (role < 12) {
            src = g_qkv + (size_t)t * 4096 + 2048 + (role - 8) * HD; w = k_nw;
            dh = sbk_hi; dl = sbk_lo; doff = (size_t)t * 1024 + (role - 8) * HD;
        } else {
            src = g_qkv + (size_t)t * 4096 + 3072 + (role - 12) * HD; rope = false;
            dh = sbv_hi; dl = sbv_lo; doff = (size_t)t * 1024 + (role - 12) * HD;
        }

        float4 a = *(const float4*)(src + cA);
        float4 b = *(const float4*)(src + cB);
        float ss = a.x*a.x + a.y*a.y + a.z*a.z + a.w*a.w
                 + b.x*b.x + b.y*b.y + b.z*b.z + b.w*b.w;
#pragma unroll
        for (int o = 16; o >= 1; o >>= 1) ss += __shfl_xor_sync(0xffffffffu, ss, o);
        float rn = rsqrtf(ss * (1.f / HD) + 1e-6f);

        float4 ya, yb;
        if (w) {
            float4 wa = *(const float4*)(w + cA);
            float4 wb = *(const float4*)(w + cB);
            ya = make_float4(a.x*rn*wa.x, a.y*rn*wa.y, a.z*rn*wa.z, a.w*rn*wa.w);
            yb = make_float4(b.x*rn*wb.x, b.y*rn*wb.y, b.z*rn*wb.z, b.w*rn*wb.w);
        } else {
            ya = make_float4(a.x*rn, a.y*rn, a.z*rn, a.w*rn);
            yb = make_float4(b.x*rn, b.y*rn, b.z*rn, b.w*rn);
        }

        float4 oa = ya, ob = yb;
        if (rope) {
            const float* cp = cosv + (size_t)t * HD;
            const float* sp = sinv + (size_t)t * HD;
            float4 ca = *(const float4*)(cp + cA), cb = *(const float4*)(cp + cB);
            float4 sa = *(const float4*)(sp + cA), sb = *(const float4*)(sp + cB);
            oa = make_float4(ya.x*ca.x - yb.x*sa.x, ya.y*ca.y - yb.y*sa.y,
                             ya.z*ca.z - yb.z*sa.z, ya.w*ca.w - yb.w*sa.w);
            ob = make_float4(yb.x*cb.x + ya.x*sb.x, yb.y*cb.y + ya.y*sb.y,
                             yb.z*cb.z + ya.z*sb.z, yb.w*cb.w + ya.w*sb.w);
        }
        store_hl4(dh, dl, doff + cA, oa);
        store_hl4(dh, dl, doff + cB, ob);
    }
}

// ---------------------------------------------------------------------------
// Sliding-window flash attention (best-measured variant, 256 threads):
// pipelined K/V loads + ping-pong softmax stats. Phase-1 fully unrolled.
// ---------------------------------------------------------------------------
__global__ __launch_bounds__(256) void attn_mma_kernel(
    const __nv_bfloat16* __restrict__ Qh, const __nv_bfloat16* __restrict__ Ql,
    const __nv_bfloat16* __restrict__ Kh, const __nv_bfloat16* __restrict__ Kl,
    const __nv_bfloat16* __restrict__ Vh, const __nv_bfloat16* __restrict__ Vl,
    __nv_bfloat16* __restrict__ Oh, __nv_bfloat16* __restrict__ Ol)
{
    extern __shared__ __nv_bfloat16 sm[];
    float* fb   = (float*)(sm + ATT_F);
    float* pmax = fb + 256;
    float* psum = fb + 384;

    const int qb = blockIdx.x, h = blockIdx.y;
    const int q0 = qb * 64;
    const int kvh = h >> 1;
    const int tid = threadIdx.x;
    const int lane = tid & 31, wid = tid >> 5;
    const int wm = wid & 3, wn = wid >> 2;
    const int wm2 = wid & 1, wn2 = wid >> 1;

    if (tid < 64) { fb[tid] = -1e30f; fb[128 + tid] = 0.f; }

#define ISSUE_K(k0)                                                            \
    {                                                                          \
        for (int i = tid; i < 2048; i += 256) {                                \
            int r = i >> 5, c = (i & 31) * 8;                                  \
            size_t g = (size_t)((k0) + r) * (NKV * HD) + kvh * HD + c;         \
            CPA16(smem_u32(sm + ATT_KH + r * DS + c), Kh + g);                 \
            CPA16(smem_u32(sm + ATT_KL + r * DS + c), Kl + g);                 \
        }                                                                      \
        asm volatile("cp.async.commit_group;");                                \
    }
#define ISSUE_V(k0)                                                            \
    {                                                                          \
        for (int i = tid; i < 2048; i += 256) {                                \
            int r = i >> 5, c = (i & 31) * 8;                                  \
            size_t g = (size_t)((k0) + r) * (NKV * HD) + kvh * HD + c;         \
            CPA16(smem_u32(sm + ATT_VH + r * DS + c), Vh + g);                 \
            CPA16(smem_u32(sm + ATT_VL + r * DS + c), Vl + g);                 \
        }                                                                      \
        asm volatile("cp.async.commit_group;");                                \
    }

    for (int i = tid; i < 2048; i += 256) {
        int r = i >> 5, c = (i & 31) * 8;
        size_t g = (size_t)(q0 + r) * HIDN + h * HD + c;
        CPA16(smem_u32(sm + ATT_QH + r * DS + c), Qh + g);
        CPA16(smem_u32(sm + ATT_QL + r * DS + c), Ql + g);
    }
    asm volatile("cp.async.commit_group;");

    float o_acc[2][8][4];
#pragma unroll
    for (int mt = 0; mt < 2; ++mt)
#pragma unroll
        for (int nt = 0; nt < 8; ++nt)
#pragma unroll
            for (int e = 0; e < 4; ++e) o_acc[mt][nt][e] = 0.f;

    int jmin = q0 - (SWIN - 1); if (jmin < 0) jmin = 0;
    const int t0 = jmin >> 6;
    const int t1 = (q0 + 63) >> 6;
    const int ntiles = t1 - t0 + 1;

    ISSUE_K(t0 * 64);
    ISSUE_V(t0 * 64);
    asm volatile("cp.async.wait_group 1;");
    __syncthreads();

    for (int kt = t0; kt <= t1; ++kt) {
        const int k0 = kt * 64;
        const int pp = (kt - t0) & 1;
        float* m_old = fb + pp * 64;
        float* m_newp = fb + (pp ^ 1) * 64;
        float* l_old = fb + 128 + pp * 64;
        float* l_newp = fb + 128 + (pp ^ 1) * 64;

        // ---- Phase 1: S = Q K^T (fully unrolled) ----
        float sacc[4][4];
#pragma unroll
        for (int nt = 0; nt < 4; ++nt)
#pragma unroll
            for (int e = 0; e < 4; ++e) sacc[nt][e] = 0.f;

#pragma unroll
        for (int ks = 0; ks < 16; ++ks) {
            unsigned int ah[4], al[4];
            {
                int row = wm * 16 + (lane & 15);
                int col = ks * 16 + (lane >> 4) * 8;
                LDSM4(ah, smem_u32(sm + ATT_QH + row * DS + col));
                LDSM4(al, smem_u32(sm + ATT_QL + row * DS + col));
            }
            unsigned int bh[2][4], bl[2][4];
#pragma unroll
            for (int p = 0; p < 2; ++p) {
                int nrow = wn * 32 + p * 16 + ((lane >> 4) << 3) + (lane & 7);
                int col = ks * 16 + ((lane >> 3) & 1) * 8;
                LDSM4(bh[p], smem_u32(sm + ATT_KH + nrow * DS + col));
                LDSM4(bl[p], smem_u32(sm + ATT_KL + nrow * DS + col));
            }
#pragma unroll
            for (int p = 0; p < 2; ++p)
#pragma unroll
                for (int o = 0; o < 4; o += 2)
                    MMA16816(sacc[p * 2 + (o >> 1)], ah, bh[p][o], bh[p][o + 1]);
#pragma unroll
            for (int p = 0; p < 2; ++p)
#pragma unroll
                for (int o = 0; o < 4; o += 2)
                    MMA16816(sacc[p * 2 + (o >> 1)], ah, bl[p][o], bl[p][o + 1]);
#pragma unroll
            for (int p = 0; p < 2; ++p)
#pragma unroll
                for (int o = 0; o < 4; o += 2)
                    MMA16816(sacc[p * 2 + (o >> 1)], al, bh[p][o], bh[p][o + 1]);
        }

        // Mask
        const int r_lo = q0 + wm * 16 + (lane >> 2);
        const int r_hi = r_lo + 8;
#pragma unroll
        for (int nt = 0; nt < 4; ++nt) {
#pragma unroll
            for (int e = 0; e < 2; ++e) {
                int j = k0 + wn * 32 + nt * 8 + (lane & 3) * 2 + e;
                if (!(j <= r_lo && r_lo - j < SWIN)) sacc[nt][e] = -1e30f;
                if (!(j <= r_hi && r_hi - j < SWIN)) sacc[nt][e + 2] = -1e30f;
            }
        }

        float mx0 = -1e30f, mx1 = -1e30f;
#pragma unroll
        for (int nt = 0; nt < 4; ++nt) {
            mx0 = fmaxf(mx0, fmaxf(sacc[nt][0], sacc[nt][1]));
            mx1 = fmaxf(mx1, fmaxf(sacc[nt][2], sacc[nt][3]));
        }
        mx0 = fmaxf(mx0, __shfl_xor_sync(0xffffffffu, mx0, 1));
        mx0 = fmaxf(mx0, __shfl_xor_sync(0xffffffffu, mx0, 2));
        mx1 = fmaxf(mx1, __shfl_xor_sync(0xffffffffu, mx1, 1));
        mx1 = fmaxf(mx1, __shfl_xor_sync(0xffffffffu, mx1, 2));
        if ((lane & 3) == 0) {
            pmax[wn * 64 + wm * 16 + (lane >> 2)]     = mx0;
            pmax[wn * 64 + wm * 16 + 8 + (lane >> 2)] = mx1;
        }
        __syncthreads();

        if (kt < t1) ISSUE_K(k0 + 64);

        float mo_t = 0.f, mn_t = 0.f;
        if (tid < 64) {
            mo_t = m_old[tid];
            mn_t = fmaxf(mo_t, fmaxf(pmax[tid], pmax[64 + tid]));
            m_newp[tid] = mn_t;
        }
        {
            const int pr0 = wm * 16 + (lane >> 2);
            const int pr1 = pr0 + 8;
            float m0v = fmaxf(m_old[pr0], fmaxf(pmax[pr0], pmax[64 + pr0]));
            float m1v = fmaxf(m_old[pr1], fmaxf(pmax[pr1], pmax[64 + pr1]));
            float s0 = 0.f, s1 = 0.f;
#pragma unroll
            for (int nt = 0; nt < 4; ++nt) {
                float p00 = (sacc[nt][0] > -1e29f) ? __expf(sacc[nt][0] - m0v) : 0.f;
                float p01 = (sacc[nt][1] > -1e29f) ? __expf(sacc[nt][1] - m0v) : 0.f;
                float p10 = (sacc[nt][2] > -1e29f) ? __expf(sacc[nt][2] - m1v) : 0.f;
                float p11 = (sacc[nt][3] > -1e29f) ? __expf(sacc[nt][3] - m1v) : 0.f;
                s0 += p00 + p01; s1 += p10 + p11;
                int colb = wn * 32 + nt * 8 + (lane & 3) * 2;
                __nv_bfloat16 h00 = __float2bfloat16_rn(p00);
                __nv_bfloat16 h01 = __float2bfloat16_rn(p01);
                __nv_bfloat16 h10 = __float2bfloat16_rn(p10);
                __nv_bfloat16 h11 = __float2bfloat16_rn(p11);
                *(__nv_bfloat162*)(sm + ATT_PH + pr0 * PSTR + colb) =
                    __halves2bfloat162(h00, h01);
                *(__nv_bfloat162*)(sm + ATT_PH + pr1 * PSTR + colb) =
                    __halves2bfloat162(h10, h11);
                *(__nv_bfloat162*)(sm + ATT_PL + pr0 * PSTR + colb) =
                    __halves2bfloat162(
                        __float2bfloat16_rn(p00 - __bfloat162float(h00)),
                        __float2bfloat16_rn(p01 - __bfloat162float(h01)));
                *(__nv_bfloat162*)(sm + ATT_PL + pr1 * PSTR + colb) =
                    __halves2bfloat162(
                        __float2bfloat16_rn(p10 - __bfloat162float(h10)),
                        __float2bfloat16_rn(p11 - __bfloat162float(h11)));
            }
            s0 += __shfl_xor_sync(0xffffffffu, s0, 1);
            s0 += __shfl_xor_sync(0xffffffffu, s0, 2);
            s1 += __shfl_xor_sync(0xffffffffu, s1, 1);
            s1 += __shfl_xor_sync(0xffffffffu, s1, 2);
            if ((lane & 3) == 0) {
                psum[wn * 64 + wm * 16 + (lane >> 2)]     = s0;
                psum[wn * 64 + wm * 16 + 8 + (lane >> 2)] = s1;
            }
        }

        // Rescale O while V(t) finishes loading
#pragma unroll
        for (int mt = 0; mt < 2; ++mt) {
            int r0 = wm2 * 32 + mt * 16 + (lane >> 2);
            int r1 = r0 + 8;
            float a0 = m_old[r0];
            float sL = __expf(a0 - fmaxf(a0, fmaxf(pmax[r0], pmax[64 + r0])));
            float a1 = m_old[r1];
            float sH = __expf(a1 - fmaxf(a1, fmaxf(pmax[r1], pmax[64 + r1])));
#pragma unroll
            for (int nt = 0; nt < 8; ++nt) {
                o_acc[mt][nt][0] *= sL; o_acc[mt][nt][1] *= sL;
                o_acc[mt][nt][2] *= sH; o_acc[mt][nt][3] *= sH;
            }
        }

        if (kt < t1) { asm volatile("cp.async.wait_group 1;"); }
        else         { asm volatile("cp.async.wait_group 0;"); }
        __syncthreads();

        if (tid < 64)
            l_newp[tid] = l_old[tid] * __expf(mo_t - mn_t)
                          + psum[tid] + psum[64 + tid];

        // ---- Phase 2: O += P V ----
#pragma unroll
        for (int ks2 = 0; ks2 < 4; ++ks2) {
            unsigned int aph[2][4], apl[2][4];
#pragma unroll
            for (int mt = 0; mt < 2; ++mt) {
                int row = wm2 * 32 + mt * 16 + (lane & 15);
                int col = ks2 * 16 + (lane >> 4) * 8;
                LDSM4(aph[mt], smem_u32(sm + ATT_PH + row * PSTR + col));
                LDSM4(apl[mt], smem_u32(sm + ATT_PL + row * PSTR + col));
            }
#pragma unroll
            for (int ng = 0; ng < 4; ++ng) {
                int vr = ks2 * 16 + ((lane >> 3) & 1) * 8 + (lane & 7);
                int vc = wn2 * 64 + ng * 16 + (lane >> 4) * 8;
                unsigned int bvh[4], bvl[4];
                LDSM4T(bvh, smem_u32(sm + ATT_VH + vr * DS + vc));
                LDSM4T(bvl, smem_u32(sm + ATT_VL + vr * DS + vc));
#pragma unroll
                for (int mt = 0; mt < 2; ++mt)
#pragma unroll
                    for (int o = 0; o < 4; o += 2)
                        MMA16816(o_acc[mt][ng * 2 + (o >> 1)],
                                 aph[mt], bvh[o], bvh[o + 1]);
#pragma unroll
                for (int mt = 0; mt < 2; ++mt)
#pragma unroll
                    for (int o = 0; o < 4; o += 2)
                        MMA16816(o_acc[mt][ng * 2 + (o >> 1)],
                                 aph[mt], bvl[o], bvl[o + 1]);
#pragma unroll
                for (int mt = 0; mt < 2; ++mt)
#pragma unroll
                    for (int o = 0; o < 4; o += 2)
                        MMA16816(o_acc[mt][ng * 2 + (o >> 1)],
                                 apl[mt], bvh[o], bvh[o + 1]);
            }
        }
        __syncthreads();

        if (kt < t1) {
            ISSUE_V(k0 + 64);
            asm volatile("cp.async.wait_group 1;");
            __syncthreads();
        }
    }

    // Epilogue
    float* l_fin = fb + 128 + (ntiles & 1) * 64;
#pragma unroll
    for (int mt = 0; mt < 2; ++mt) {
        int rL = wm2 * 32 + mt * 16 + (lane >> 2);
        int rH = rL + 8;
        float invL = 1.f / l_fin[rL];
        float invH = 1.f / l_fin[rH];
#pragma unroll
        for (int nt = 0; nt < 8; ++nt) {
            int col = wn2 * 64 + nt * 8 + (lane & 3) * 2;
            size_t gL = (size_t)(q0 + rL) * HIDN + h * HD + col;
            size_t gH = (size_t)(q0 + rH) * HIDN + h * HD + col;
            float v0 = o_acc[mt][nt][0] * invL, v1 = o_acc[mt][nt][1] * invL;
            float v2 = o_acc[mt][nt][2] * invH, v3 = o_acc[mt][nt][3] * invH;
            __nv_bfloat16 h0 = __float2bfloat16_rn(v0), h1 = __float2bfloat16_rn(v1);
            __nv_bfloat16 h2 = __float2bfloat16_rn(v2), h3 = __float2bfloat16_rn(v3);
            *(__nv_bfloat162*)(Oh + gL) = __halves2bfloat162(h0, h1);
            *(__nv_bfloat162*)(Oh + gH) = __halves2bfloat162(h2, h3);
            *(__nv_bfloat162*)(Ol + gL) = __halves2bfloat162(
                __float2bfloat16_rn(v0 - __bfloat162float(h0)),
                __float2bfloat16_rn(v1 - __bfloat162float(h1)));
            *(__nv_bfloat162*)(Ol + gH) = __halves2bfloat162(
                __float2bfloat16_rn(v2 - __bfloat162float(h2)),
                __float2bfloat16_rn(v3 - __bfloat162float(h3)));
        }
    }
#undef ISSUE_K
#undef ISSUE_V
}

// ---------------------------------------------------------------------------
extern "C" void kernel_launch(void* const* d_in, const int* in_sizes, int n_in,
                              void* d_out, int out_size)
{
    const float* hidden = (const float*)d_in[0];
    const float* cosv   = (const float*)d_in[1];
    const float* sinv   = (const float*)d_in[2];
    const float* q_w    = (const float*)d_in[3];
    const float* k_w    = (const float*)d_in[4];
    const float* v_w    = (const float*)d_in[5];
    const float* o_w    = (const float*)d_in[6];
    const float* q_nw   = (const float*)d_in[7];
    const float* k_nw   = (const float*)d_in[8];

    float* qkvp;
    cudaGetSymbolAddress((void**)&qkvp, g_qkv);

    __nv_bfloat16 *hid_h, *hid_l, *w_h, *w_l, *ow_h, *ow_l, *at_h, *at_l,
                  *q_h, *q_l, *k_h, *k_l, *v_h, *v_l;
    cudaGetSymbolAddress((void**)&hid_h, sb_hid_hi);
    cudaGetSymbolAddress((void**)&hid_l, sb_hid_lo);
    cudaGetSymbolAddress((void**)&w_h, sb_w_hi);
    cudaGetSymbolAddress((void**)&w_l, sb_w_lo);
    cudaGetSymbolAddress((void**)&ow_h, sb_ow_hi);
    cudaGetSymbolAddress((void**)&ow_l, sb_ow_lo);
    cudaGetSymbolAddress((void**)&at_h, sb_at_hi);
    cudaGetSymbolAddress((void**)&at_l, sb_at_lo);
    cudaGetSymbolAddress((void**)&q_h, sbq_hi);
    cudaGetSymbolAddress((void**)&q_l, sbq_lo);
    cudaGetSymbolAddress((void**)&k_h, sbk_hi);
    cudaGetSymbolAddress((void**)&k_l, sbk_lo);
    cudaGetSymbolAddress((void**)&v_h, sbv_hi);
    cudaGetSymbolAddress((void**)&v_l, sbv_lo);

    const int gemm_smem = 2 * 4 * GSTG * (int)sizeof(__nv_bfloat16);
    cudaFuncSetAttribute(gemm_bf16split, cudaFuncAttributeMaxDynamicSharedMemorySize,
                         gemm_smem);
    cudaFuncSetAttribute(attn_mma_kernel, cudaFuncAttributeMaxDynamicSharedMemorySize,
                         ATT_SMEM_BYTES);

    SplitSegs segs;
    long n_hid = (long)T_TOK * HIDN / 4;
    long n_qw  = (long)HIDN * HIDN / 4;
    long n_kw  = (long)NKV * HD * HIDN / 4;
    segs.src[0] = (const float4*)hidden; segs.hi[0] = (__nv_bfloat162*)hid_h;
    segs.lo[0] = (__nv_bfloat162*)hid_l; segs.end[0] = n_hid;
    segs.src[1] = (const float4*)q_w;    segs.hi[1] = (__nv_bfloat162*)w_h;
    segs.lo[1] = (__nv_bfloat162*)w_l;   segs.end[1] = segs.end[0] + n_qw;
    segs.src[2] = (const float4*)k_w;
    segs.hi[2] = (__nv_bfloat162*)(w_h + (size_t)HIDN * HIDN);
    segs.lo[2] = (__nv_bfloat162*)(w_l + (size_t)HIDN * HIDN);
    segs.end[2] = segs.end[1] + n_kw;
    segs.src[3] = (const float4*)v_w;
    segs.hi[3] = (__nv_bfloat162*)(w_h + (size_t)HIDN * HIDN + (size_t)NKV * HD * HIDN);
    segs.lo[3] = (__nv_bfloat162*)(w_l + (size_t)HIDN * HIDN + (size_t)NKV * HD * HIDN);
    segs.end[3] = segs.end[2] + n_kw;
    segs.src[4] = (const float4*)o_w;    segs.hi[4] = (__nv_bfloat162*)ow_h;
    segs.lo[4] = (__nv_bfloat162*)ow_l;  segs.end[4] = segs.end[3] + n_qw;
    long total_thr = segs.end[4] / 4;
    split_all_kernel<<<(unsigned)((total_thr + 255) / 256), 256>>>(segs);

    gemm_bf16split<<<dim3(4096 / 128, T_TOK / 128), 256, gemm_smem>>>(
        hid_h, hid_l, w_h, w_l, qkvp, T_TOK, 4096, HIDN);

    norm_rope_kernel<<<T_TOK, 256>>>(cosv, sinv, q_nw, k_nw);

    attn_mma_kernel<<<dim3(T_TOK / 64, NH), 256, ATT_SMEM_BYTES>>>(
        q_h, q_l, k_h, k_l, v_h, v_l, at_h, at_l);

    gemm_bf16split<<<dim3(HIDN / 128, T_TOK / 128), 256, gemm_smem>>>(
        at_h, at_l, ow_h, ow_l, (float*)d_out, T_TOK, HIDN, HIDN);
}